// round 1
// baseline (speedup 1.0000x reference)
#include <cuda_runtime.h>

// Reverb via FFT convolution:
//   y[i] = sum_j audio[i+j] * ir[j]   (audio zero-extended), i in [0,N)
//   out  = y / max|y|
//
// nfft = 2^22 >= N + 2(M-1) = 3,086,998  -> no circular aliasing.
// One complex forward FFT of z = audio + i*flip(ir)  (two real FFTs in one),
// spectral unpack+multiply (+conj), one more forward FFT = inverse, slice+scale,
// global max-abs reduce, normalize.

#define NFFT     (1 << 22)
#define NSTAGES  11            // radix-4: 4^11 = 2^22

__device__ float2 g_bufA[NFFT];
__device__ float2 g_bufB[NFFT];
__device__ unsigned int g_max_bits;

__device__ __forceinline__ float2 cmul(float2 a, float2 b) {
    return make_float2(fmaf(a.x, b.x, -(a.y * b.y)),
                       fmaf(a.x, b.y,  (a.y * b.x)));
}

// z[n] = audio_pad[n] + i * ir[M-1-n]  (flipped ir, zero-padded)
__global__ void pack_kernel(const float* __restrict__ audio, int N,
                            const float* __restrict__ ir, int M) {
    int i = blockIdx.x * blockDim.x + threadIdx.x;
    if (i == 0) g_max_bits = 0u;
    float re = (i < N) ? audio[i] : 0.0f;
    float im = (i < M) ? ir[M - 1 - i] : 0.0f;
    g_bufA[i] = make_float2(re, im);
}

// One Stockham radix-4 DIF stage (OTFFT formulation, autosorting).
// total threads = NFFT/4. q = t & (s-1), p = t >> s_log2, m = n_cur/4.
// reads  x[q + s*(p + u*m)], u=0..3
// writes y[q + s*(4p + r)] = w_r^p * B_r,  w1 = e^{-2*pi*i*p/n_cur}
__global__ void fft_stage(const float2* __restrict__ x, float2* __restrict__ y,
                          int s_log2, int m, float theta0) {
    int t = blockIdx.x * blockDim.x + threadIdx.x;
    int s = 1 << s_log2;
    int q = t & (s - 1);
    int p = t >> s_log2;

    float2 a = x[q + ((p        ) << s_log2)];
    float2 b = x[q + ((p +   m  ) << s_log2)];
    float2 c = x[q + ((p + 2*m  ) << s_log2)];
    float2 d = x[q + ((p + 3*m  ) << s_log2)];

    float sn, cs;
    sincosf(theta0 * (float)p, &sn, &cs);
    float2 w1 = make_float2(cs, -sn);       // e^{-i*theta0*p}
    float2 w2 = cmul(w1, w1);
    float2 w3 = cmul(w2, w1);

    float2 apc = make_float2(a.x + c.x, a.y + c.y);
    float2 amc = make_float2(a.x - c.x, a.y - c.y);
    float2 bpd = make_float2(b.x + d.x, b.y + d.y);
    float2 bmd = make_float2(b.x - d.x, b.y - d.y);

    float2 e0 = make_float2(apc.x + bpd.x, apc.y + bpd.y);   // a+b+c+d
    float2 e1 = make_float2(amc.x + bmd.y, amc.y - bmd.x);   // (a-c) - i(b-d)
    float2 e2 = make_float2(apc.x - bpd.x, apc.y - bpd.y);   // (a+c) - (b+d)
    float2 e3 = make_float2(amc.x - bmd.y, amc.y + bmd.x);   // (a-c) + i(b-d)

    int base = q + ((4 * p) << s_log2);
    y[base        ] = e0;
    y[base +     s] = cmul(w1, e1);
    y[base + 2 * s] = cmul(w2, e2);
    y[base + 3 * s] = cmul(w3, e3);
}

// Unpack the packed real-pair FFT, multiply spectra, conjugate (for inverse
// via forward transform):
//   A[k] = (Z[k] + conj(Z[N-k]))/2,  H[k] = (Z[k] - conj(Z[N-k]))/(2i)
//   out[k] = conj(A[k]*H[k])
__global__ void specmul_kernel(const float2* __restrict__ Z,
                               float2* __restrict__ out) {
    int k = blockIdx.x * blockDim.x + threadIdx.x;
    float2 zk = Z[k];
    float2 zn = Z[(NFFT - k) & (NFFT - 1)];
    float2 A  = make_float2(0.5f * (zk.x + zn.x), 0.5f * (zk.y - zn.y));
    float2 Dv = make_float2(zk.x - zn.x, zk.y + zn.y);   // Z[k] - conj(Z[N-k])
    float2 H  = make_float2(0.5f * Dv.y, -0.5f * Dv.x);  // Dv * (-i/2)
    float2 Y  = cmul(A, H);
    out[k] = make_float2(Y.x, -Y.y);
}

// y[i] = real(W[M-1+i]) / NFFT ; write raw y to out and reduce max|y|.
__global__ void finalize_kernel(const float2* __restrict__ W,
                                float* __restrict__ out, int N, int M) {
    int i = blockIdx.x * blockDim.x + threadIdx.x;
    float v = 0.0f;
    if (i < N) {
        v = W[(M - 1) + i].x * (1.0f / (float)NFFT);
        out[i] = v;
    }
    float av = fabsf(v);
    #pragma unroll
    for (int off = 16; off > 0; off >>= 1)
        av = fmaxf(av, __shfl_xor_sync(0xffffffffu, av, off));
    __shared__ float warpmax[8];
    int lane = threadIdx.x & 31, w = threadIdx.x >> 5;
    if (lane == 0) warpmax[w] = av;
    __syncthreads();
    if (threadIdx.x == 0) {
        float mx = warpmax[0];
        #pragma unroll
        for (int j = 1; j < 8; j++) mx = fmaxf(mx, warpmax[j]);
        atomicMax(&g_max_bits, __float_as_uint(mx));   // valid: values >= 0
    }
}

__global__ void norm_kernel(float* __restrict__ out, int N) {
    int i = blockIdx.x * blockDim.x + threadIdx.x;
    if (i < N) {
        float mx = __uint_as_float(g_max_bits);
        out[i] = out[i] / mx;
    }
}

extern "C" void kernel_launch(void* const* d_in, const int* in_sizes, int n_in,
                              void* d_out, int out_size) {
    const float* audio = (const float*)d_in[0];
    const float* ir    = (const float*)d_in[1];
    const int N = in_sizes[0];
    const int M = in_sizes[1];
    float* out = (float*)d_out;

    float2 *A = nullptr, *B = nullptr;
    cudaGetSymbolAddress((void**)&A, g_bufA);   // address query only, capture-safe
    cudaGetSymbolAddress((void**)&B, g_bufB);

    const int TPB = 256;
    pack_kernel<<<NFFT / TPB, TPB>>>(audio, N, ir, M);

    // Forward FFT of packed signal: A -> ... -> B (11 stages, ping-pong)
    float2* src = A; float2* dst = B;
    int n_cur = NFFT, s_log2 = 0;
    for (int st = 0; st < NSTAGES; st++) {
        float theta0 = (float)(6.283185307179586 / (double)n_cur);
        fft_stage<<<(NFFT / 4) / TPB, TPB>>>(src, dst, s_log2, n_cur >> 2, theta0);
        float2* tmp = src; src = dst; dst = tmp;
        n_cur >>= 2; s_log2 += 2;
    }
    // spectrum Z in src (== B)

    specmul_kernel<<<NFFT / TPB, TPB>>>(src, dst);   // B -> A (conj(Y))

    // Forward FFT again == (scaled, conjugated) inverse: A -> ... -> B
    src = A; dst = B;
    n_cur = NFFT; s_log2 = 0;
    for (int st = 0; st < NSTAGES; st++) {
        float theta0 = (float)(6.283185307179586 / (double)n_cur);
        fft_stage<<<(NFFT / 4) / TPB, TPB>>>(src, dst, s_log2, n_cur >> 2, theta0);
        float2* tmp = src; src = dst; dst = tmp;
        n_cur >>= 2; s_log2 += 2;
    }
    // time-domain result in src (== B)

    int nblk = (N + TPB - 1) / TPB;
    finalize_kernel<<<nblk, TPB>>>(src, out, N, M);
    norm_kernel<<<nblk, TPB>>>(out, N);
}

// round 2
// speedup vs baseline: 1.5935x; 1.5935x over previous
#include <cuda_runtime.h>

// Reverb via four-step FFT convolution.
//   y[i] = sum_j audio[i+j]*ir[j],  out = y / max|y|
//
// NFFT = 2^22 = N1*N2, N1=1024, N2=4096.
// Decomposition: n = n1 + N1*n2, k = k2 + N2*k1:
//   X[k2 + N2*k1] = FFT_{N1 over n1}( e^{-2pi i n1 k2/N} * FFT_{N2 over n2}( x[n1+N1*n2] ) )
// Pass A (fft_rows): per n1, 4096-pt FFT in smem + twiddle. Needs input stored
//   row-contiguous G0[n1*N2+n2] = x[n1+N1*n2]  (transpose fused into pack/specmul).
// Pass B (fft_cols): per k2-tile, 1024-pt FFTs in smem; writes natural order.
//
// Forward FFT of z = audio + i*flip(ir) packs both real FFTs into one.
// Inverse via conj trick, conj fused into specmul. Max-abs reduction fused
// into the last fft_cols pass; final kernel just divides.

#define NFFT   (1 << 22)
#define N1     1024
#define N2     4096
#define LOG2N1 10
#define LOG2N2 12
#define TILE   4          // k2 columns per fft_cols block
#define LOG2TILE 2

__device__ float2 g_bufA[NFFT];
__device__ float2 g_bufB[NFFT];
__device__ unsigned int g_max_bits;

__device__ __forceinline__ float2 cmul(float2 a, float2 b) {
    return make_float2(fmaf(a.x, b.x, -(a.y * b.y)),
                       fmaf(a.x, b.y,  (a.y * b.x)));
}

// One radix-4 Stockham butterfly on smem arrays with element stride STRIDE.
template<int STRIDE>
__device__ __forceinline__ void bfly(const float2* __restrict__ src,
                                     float2* __restrict__ dst,
                                     int q, int p, int slog, int m,
                                     float th0, int boff) {
    int s = 1 << slog;
    float2 a = src[(q + ((p        ) << slog)) * STRIDE + boff];
    float2 b = src[(q + ((p +   m  ) << slog)) * STRIDE + boff];
    float2 c = src[(q + ((p + 2*m  ) << slog)) * STRIDE + boff];
    float2 d = src[(q + ((p + 3*m  ) << slog)) * STRIDE + boff];

    float sn, cs;
    sincosf(th0 * (float)p, &sn, &cs);
    float2 w1 = make_float2(cs, -sn);
    float2 w2 = cmul(w1, w1);
    float2 w3 = cmul(w2, w1);

    float2 apc = make_float2(a.x + c.x, a.y + c.y);
    float2 amc = make_float2(a.x - c.x, a.y - c.y);
    float2 bpd = make_float2(b.x + d.x, b.y + d.y);
    float2 bmd = make_float2(b.x - d.x, b.y - d.y);

    float2 e0 = make_float2(apc.x + bpd.x, apc.y + bpd.y);
    float2 e1 = make_float2(amc.x + bmd.y, amc.y - bmd.x);
    float2 e2 = make_float2(apc.x - bpd.x, apc.y - bpd.y);
    float2 e3 = make_float2(amc.x - bmd.y, amc.y + bmd.x);

    int base = q + ((4 * p) << slog);
    dst[(base        ) * STRIDE + boff] = e0;
    dst[(base +     s) * STRIDE + boff] = cmul(w1, e1);
    dst[(base + 2 * s) * STRIDE + boff] = cmul(w2, e2);
    dst[(base + 3 * s) * STRIDE + boff] = cmul(w3, e3);
}

// ---------------- pack: z[n1+N1*n2] = audio + i*flip(ir), write transposed
// G0[n1*N2 + n2]. 32x32 smem tile transpose; also resets the max accumulator.
__global__ void pack_kernel(const float* __restrict__ audio, int N,
                            const float* __restrict__ ir, int M,
                            float2* __restrict__ G0) {
    __shared__ float2 tile[32][33];
    if (blockIdx.x == 0 && blockIdx.y == 0 && threadIdx.x == 0 && threadIdx.y == 0)
        g_max_bits = 0u;
    int n2_0 = blockIdx.x * 32;
    int n1_0 = blockIdx.y * 32;
    int tx = threadIdx.x;
    #pragma unroll
    for (int r = 0; r < 4; r++) {
        int ty = threadIdx.y + r * 8;
        int i = (n1_0 + tx) + ((n2_0 + ty) << LOG2N1);   // contiguous in tx
        float re = (i < N) ? audio[i] : 0.0f;
        float im = (i < M) ? ir[M - 1 - i] : 0.0f;
        tile[ty][tx] = make_float2(re, im);
    }
    __syncthreads();
    #pragma unroll
    for (int r = 0; r < 4; r++) {
        int ty = threadIdx.y + r * 8;
        G0[((size_t)(n1_0 + ty) << LOG2N2) + n2_0 + tx] = tile[tx][ty];
    }
}

// ---------------- fft_rows: per-n1 4096-pt FFT in smem, fused inter-dim twiddle.
__global__ void fft_rows(const float2* __restrict__ in, float2* __restrict__ out) {
    extern __shared__ float2 sm[];                 // 2 * 4096 float2 = 64 KB
    float2* bufA = sm;
    float2* bufB = sm + N2;
    int n1 = blockIdx.x;
    const float2* row = in + ((size_t)n1 << LOG2N2);

    for (int i = threadIdx.x; i < N2; i += blockDim.x) bufA[i] = row[i];
    __syncthreads();

    float2* src = bufA; float2* dst = bufB;
    int n_cur = N2, slog = 0;
    #pragma unroll
    for (int st = 0; st < 6; st++) {               // 4096 = 4^6
        int m = n_cur >> 2;
        float th0 = 6.2831853071795864769f / (float)n_cur;
        #pragma unroll
        for (int t = threadIdx.x; t < (N2 >> 2); t += 512) {
            int q = t & ((1 << slog) - 1);
            int p = t >> slog;
            bfly<1>(src, dst, q, p, slog, m, th0, 0);
        }
        __syncthreads();
        float2* tmp = src; src = dst; dst = tmp;
        n_cur >>= 2; slog += 2;
    }
    // 6 swaps -> result back in bufA (== src)

    float2* o = out + ((size_t)n1 << LOG2N2);
    const float c0 = 6.2831853071795864769f / (float)NFFT;
    for (int k = threadIdx.x; k < N2; k += blockDim.x) {
        unsigned idx = ((unsigned)n1 * (unsigned)k) & (NFFT - 1);
        float sn, cs;
        sincosf(c0 * (float)idx, &sn, &cs);
        o[k] = cmul(src[k], make_float2(cs, -sn));
    }
}

// ---------------- fft_cols: TILE k2 columns, 1024-pt FFTs in smem.
// Writes natural order X[k2 + N2*k1]. Optionally reduces max|re| over [lo,hi).
__global__ void fft_cols(const float2* __restrict__ in, float2* __restrict__ out,
                         int doMax, int lo, int hi) {
    extern __shared__ float2 sm[];                 // 2 * 1024*TILE float2 = 64 KB
    float2* bufA = sm;
    float2* bufB = sm + N1 * TILE;
    int k20 = blockIdx.x * TILE;

    for (int e = threadIdx.x; e < N1 * TILE; e += blockDim.x) {
        int b  = e & (TILE - 1);
        int n1 = e >> LOG2TILE;
        bufA[n1 * TILE + b] = in[((size_t)n1 << LOG2N2) + k20 + b];
    }
    __syncthreads();

    float2* src = bufA; float2* dst = bufB;
    int n_cur = N1, slog = 0;
    #pragma unroll
    for (int st = 0; st < 5; st++) {               // 1024 = 4^5
        int m = n_cur >> 2;
        float th0 = 6.2831853071795864769f / (float)n_cur;
        #pragma unroll
        for (int e = threadIdx.x; e < (N1 >> 2) * TILE; e += 512) {
            int b = e & (TILE - 1);
            int t = e >> LOG2TILE;
            int q = t & ((1 << slog) - 1);
            int p = t >> slog;
            bfly<TILE>(src, dst, q, p, slog, m, th0, b);
        }
        __syncthreads();
        float2* tmp = src; src = dst; dst = tmp;
        n_cur >>= 2; slog += 2;
    }
    // 5 swaps -> result in bufB (== src)

    float localmax = 0.0f;
    for (int e = threadIdx.x; e < N1 * TILE; e += blockDim.x) {
        int b  = e & (TILE - 1);
        int k1 = e >> LOG2TILE;
        float2 v = src[k1 * TILE + b];
        int k = k20 + b + (k1 << LOG2N2);
        out[k] = v;
        if (doMax && k >= lo && k < hi)
            localmax = fmaxf(localmax, fabsf(v.x));
    }
    if (doMax) {
        #pragma unroll
        for (int off = 16; off > 0; off >>= 1)
            localmax = fmaxf(localmax, __shfl_xor_sync(0xffffffffu, localmax, off));
        __shared__ float wmax[16];
        int lane = threadIdx.x & 31, w = threadIdx.x >> 5;
        if (lane == 0) wmax[w] = localmax;
        __syncthreads();
        if (threadIdx.x == 0) {
            float mx = wmax[0];
            #pragma unroll
            for (int j = 1; j < 16; j++) mx = fmaxf(mx, wmax[j]);
            atomicMax(&g_max_bits, __float_as_uint(mx));   // values >= 0
        }
    }
}

// ---------------- specmul: unpack packed real-pair spectrum, multiply, conj,
// and write transposed layout W0[n1*N2 + n2] = Yc[n1 + N1*n2] (tile transpose).
__global__ void specmul_t(const float2* __restrict__ Z, float2* __restrict__ W) {
    __shared__ float2 tile[32][33];
    int n2_0 = blockIdx.x * 32;
    int n1_0 = blockIdx.y * 32;
    int tx = threadIdx.x;
    #pragma unroll
    for (int r = 0; r < 4; r++) {
        int ty = threadIdx.y + r * 8;
        int i = (n1_0 + tx) + ((n2_0 + ty) << LOG2N1);
        float2 zk = Z[i];
        float2 zn = Z[(NFFT - i) & (NFFT - 1)];
        float2 A  = make_float2(0.5f * (zk.x + zn.x), 0.5f * (zk.y - zn.y));
        float2 Dv = make_float2(zk.x - zn.x, zk.y + zn.y);
        float2 H  = make_float2(0.5f * Dv.y, -0.5f * Dv.x);
        float2 Y  = cmul(A, H);
        tile[ty][tx] = make_float2(Y.x, -Y.y);     // conj for inverse-via-forward
    }
    __syncthreads();
    #pragma unroll
    for (int r = 0; r < 4; r++) {
        int ty = threadIdx.y + r * 8;
        W[((size_t)(n1_0 + ty) << LOG2N2) + n2_0 + tx] = tile[tx][ty];
    }
}

// ---------------- final: out[i] = W[M-1+i].x / max|.x|  (scales cancel)
__global__ void final_kernel(const float2* __restrict__ W,
                             float* __restrict__ out, int N, int M) {
    int i = blockIdx.x * blockDim.x + threadIdx.x;
    if (i < N) {
        float mx = __uint_as_float(g_max_bits);
        out[i] = W[(M - 1) + i].x / mx;
    }
}

extern "C" void kernel_launch(void* const* d_in, const int* in_sizes, int n_in,
                              void* d_out, int out_size) {
    const float* audio = (const float*)d_in[0];
    const float* ir    = (const float*)d_in[1];
    const int N = in_sizes[0];
    const int M = in_sizes[1];
    float* out = (float*)d_out;

    float2 *A = nullptr, *B = nullptr;
    cudaGetSymbolAddress((void**)&A, g_bufA);
    cudaGetSymbolAddress((void**)&B, g_bufB);

    cudaFuncSetAttribute(fft_rows, cudaFuncAttributeMaxDynamicSharedMemorySize, 2 * N2 * (int)sizeof(float2));
    cudaFuncSetAttribute(fft_cols, cudaFuncAttributeMaxDynamicSharedMemorySize, 2 * N1 * TILE * (int)sizeof(float2));

    dim3 tblk(32, 8);
    dim3 tgrid(N2 / 32, N1 / 32);

    // pack (with transpose): -> A  [A = G0: row-contiguous in n2]
    pack_kernel<<<tgrid, tblk>>>(audio, N, ir, M, A);

    // forward FFT: A -> B (rows), B -> A (cols, natural-order spectrum Z)
    fft_rows<<<N1, 512, 2 * N2 * sizeof(float2)>>>(A, B);
    fft_cols<<<N2 / TILE, 512, 2 * N1 * TILE * sizeof(float2)>>>(B, A, 0, 0, 0);

    // spectral multiply + conj + transpose: A -> B
    specmul_t<<<tgrid, tblk>>>(A, B);

    // inverse (forward of conj): B -> A (rows), A -> B (cols + max reduce)
    fft_rows<<<N1, 512, 2 * N2 * sizeof(float2)>>>(B, A);
    fft_cols<<<N2 / TILE, 512, 2 * N1 * TILE * sizeof(float2)>>>(A, B, 1, M - 1, M - 1 + N);

    // normalize slice
    final_kernel<<<(N + 255) / 256, 256>>>(B, out, N, M);
}

// round 3
// speedup vs baseline: 2.0304x; 1.2742x over previous
#include <cuda_runtime.h>

// Reverb via four-step FFT convolution. NFFT = 2^22 = N1*N2 (1024 x 4096).
//   y[i] = sum_j audio[i+j]*ir[j],  out = y / max|y|
// Forward FFT of z = audio + i*flip(ir) (both real FFTs in one complex FFT),
// spectral unpack+multiply+conj, forward FFT again = inverse, slice, max-norm.
//
// fft_rows: 4096-pt FFT per n1 (contiguous rows), inter-dim twiddle fused
//           into the LAST radix-4 stage (whose internal twiddles are trivial),
//           first stage fused with the global load.
// fft_cols: 1024-pt FFTs over TILE columns, first/last stages fused with
//           global load/store, max-abs reduction fused into last inverse pass.
// All twiddles via __sincosf (args in [0, 2pi), plenty accurate for 1e-3 tol).

#define NFFT   (1 << 22)
#define N1     1024
#define N2     4096
#define LOG2N1 10
#define LOG2N2 12
#define TILE   4
#define LOG2TILE 2

__device__ float2 g_bufA[NFFT];
__device__ float2 g_bufB[NFFT];
__device__ unsigned int g_max_bits;

__device__ __forceinline__ float2 cmul(float2 a, float2 b) {
    return make_float2(fmaf(a.x, b.x, -(a.y * b.y)),
                       fmaf(a.x, b.y,  (a.y * b.x)));
}

// radix-4 DIF core: given a,b,c,d returns e0..e3 (before output twiddles)
__device__ __forceinline__ void r4core(float2 a, float2 b, float2 c, float2 d,
                                       float2& e0, float2& e1, float2& e2, float2& e3) {
    float2 apc = make_float2(a.x + c.x, a.y + c.y);
    float2 amc = make_float2(a.x - c.x, a.y - c.y);
    float2 bpd = make_float2(b.x + d.x, b.y + d.y);
    float2 bmd = make_float2(b.x - d.x, b.y - d.y);
    e0 = make_float2(apc.x + bpd.x, apc.y + bpd.y);
    e1 = make_float2(amc.x + bmd.y, amc.y - bmd.x);
    e2 = make_float2(apc.x - bpd.x, apc.y - bpd.y);
    e3 = make_float2(amc.x - bmd.y, amc.y + bmd.x);
}

__device__ __forceinline__ float2 twid(float ang) {   // e^{-i ang}
    float sn, cs;
    __sincosf(ang, &sn, &cs);
    return make_float2(cs, -sn);
}

// ---------------- pack: z = audio + i*flip(ir), transposed G0[n1*N2+n2]
__global__ void pack_kernel(const float* __restrict__ audio, int N,
                            const float* __restrict__ ir, int M,
                            float2* __restrict__ G0) {
    __shared__ float2 tile[32][33];
    if (blockIdx.x == 0 && blockIdx.y == 0 && threadIdx.x == 0 && threadIdx.y == 0)
        g_max_bits = 0u;
    int n2_0 = blockIdx.x * 32;
    int n1_0 = blockIdx.y * 32;
    int tx = threadIdx.x;
    #pragma unroll
    for (int r = 0; r < 4; r++) {
        int ty = threadIdx.y + r * 8;
        int i = (n1_0 + tx) + ((n2_0 + ty) << LOG2N1);
        float re = (i < N) ? audio[i] : 0.0f;
        float im = (i < M) ? ir[M - 1 - i] : 0.0f;
        tile[ty][tx] = make_float2(re, im);
    }
    __syncthreads();
    #pragma unroll
    for (int r = 0; r < 4; r++) {
        int ty = threadIdx.y + r * 8;
        G0[((size_t)(n1_0 + ty) << LOG2N2) + n2_0 + tx] = tile[tx][ty];
    }
}

// ---------------- fft_rows: 4096-pt FFT, 512 threads, stages 0/5 fused w/ gmem
__global__ void fft_rows(const float2* __restrict__ in, float2* __restrict__ out) {
    extern __shared__ float2 sm[];                 // 2 * 4096 float2 = 64 KB
    float2* bA = sm;
    float2* bB = sm + N2;
    int n1 = blockIdx.x;
    const float2* row = in + ((size_t)n1 << LOG2N2);
    float2* orow = out + ((size_t)n1 << LOG2N2);

    // stage 0: n_cur=4096, s=1, m=1024; gmem -> bA
    {
        const float th0 = 6.2831853071795864769f / 4096.0f;
        #pragma unroll
        for (int p = threadIdx.x; p < 1024; p += 512) {
            float2 a = row[p], b = row[p + 1024], c = row[p + 2048], d = row[p + 3072];
            float2 w1 = twid(th0 * (float)p);
            float2 w2 = cmul(w1, w1), w3 = cmul(w2, w1);
            float2 e0, e1, e2, e3;
            r4core(a, b, c, d, e0, e1, e2, e3);
            int base = 4 * p;
            bA[base] = e0; bA[base + 1] = cmul(w1, e1);
            bA[base + 2] = cmul(w2, e2); bA[base + 3] = cmul(w3, e3);
        }
    }
    __syncthreads();

    // stages 1..4 in smem (slog = 2,4,6,8)
    float2* src = bA; float2* dst = bB;
    #pragma unroll
    for (int st = 1; st <= 4; st++) {
        int slog = 2 * st;
        int n_cur = N2 >> slog;
        int m = n_cur >> 2;
        float th0 = 6.2831853071795864769f / (float)n_cur;
        #pragma unroll
        for (int t = threadIdx.x; t < 1024; t += 512) {
            int q = t & ((1 << slog) - 1);
            int p = t >> slog;
            float2 a = src[q + ((p      ) << slog)];
            float2 b = src[q + ((p +  m ) << slog)];
            float2 c = src[q + ((p + 2*m) << slog)];
            float2 d = src[q + ((p + 3*m) << slog)];
            float2 w1 = twid(th0 * (float)p);
            float2 w2 = cmul(w1, w1), w3 = cmul(w2, w1);
            float2 e0, e1, e2, e3;
            r4core(a, b, c, d, e0, e1, e2, e3);
            int base = q + ((4 * p) << slog);
            int s = 1 << slog;
            dst[base] = e0; dst[base + s] = cmul(w1, e1);
            dst[base + 2*s] = cmul(w2, e2); dst[base + 3*s] = cmul(w3, e3);
        }
        __syncthreads();
        float2* tmp = src; src = dst; dst = tmp;
    }
    // after 4 swaps src == bA

    // stage 5: n_cur=4, s=1024, p=0 (trivial internal twiddles); fuse the
    // inter-dimension twiddle tw(n1*k / NFFT) and the gmem store.
    {
        const float c0 = 6.2831853071795864769f / (float)NFFT;
        #pragma unroll
        for (int q = threadIdx.x; q < 1024; q += 512) {
            float2 a = src[q], b = src[q + 1024], c = src[q + 2048], d = src[q + 3072];
            float2 e0, e1, e2, e3;
            r4core(a, b, c, d, e0, e1, e2, e3);
            unsigned un1 = (unsigned)n1;
            unsigned k0 = (un1 * (unsigned)q)          & (NFFT - 1);
            unsigned k1 = (un1 * (unsigned)(q + 1024)) & (NFFT - 1);
            unsigned k2 = (un1 * (unsigned)(q + 2048)) & (NFFT - 1);
            unsigned k3 = (un1 * (unsigned)(q + 3072)) & (NFFT - 1);
            orow[q       ] = cmul(e0, twid(c0 * (float)k0));
            orow[q + 1024] = cmul(e1, twid(c0 * (float)k1));
            orow[q + 2048] = cmul(e2, twid(c0 * (float)k2));
            orow[q + 3072] = cmul(e3, twid(c0 * (float)k3));
        }
    }
}

// ---------------- fft_cols: 1024-pt FFTs over TILE columns, 512 threads.
// stage 0 fused with gmem load, stage 4 fused with gmem store (+max reduce).
__global__ void fft_cols(const float2* __restrict__ in, float2* __restrict__ out,
                         int doMax, int lo, int hi) {
    extern __shared__ float2 sm[];                 // 2 * 1024*TILE float2 = 64 KB
    float2* bA = sm;
    float2* bB = sm + N1 * TILE;
    int k20 = blockIdx.x * TILE;

    // stage 0: n_cur=1024, s=1, m=256; gmem -> bA
    {
        const float th0 = 6.2831853071795864769f / 1024.0f;
        #pragma unroll
        for (int e = threadIdx.x; e < 256 * TILE; e += 512) {
            int b = e & (TILE - 1);
            int p = e >> LOG2TILE;
            float2 a = in[((size_t)(p      ) << LOG2N2) + k20 + b];
            float2 bb= in[((size_t)(p + 256) << LOG2N2) + k20 + b];
            float2 c = in[((size_t)(p + 512) << LOG2N2) + k20 + b];
            float2 d = in[((size_t)(p + 768) << LOG2N2) + k20 + b];
            float2 w1 = twid(th0 * (float)p);
            float2 w2 = cmul(w1, w1), w3 = cmul(w2, w1);
            float2 e0, e1, e2, e3;
            r4core(a, bb, c, d, e0, e1, e2, e3);
            int base = 4 * p;
            bA[(base    ) * TILE + b] = e0;
            bA[(base + 1) * TILE + b] = cmul(w1, e1);
            bA[(base + 2) * TILE + b] = cmul(w2, e2);
            bA[(base + 3) * TILE + b] = cmul(w3, e3);
        }
    }
    __syncthreads();

    // stages 1..3 (slog = 2,4,6)
    float2* src = bA; float2* dst = bB;
    #pragma unroll
    for (int st = 1; st <= 3; st++) {
        int slog = 2 * st;
        int n_cur = N1 >> slog;
        int m = n_cur >> 2;
        float th0 = 6.2831853071795864769f / (float)n_cur;
        #pragma unroll
        for (int e = threadIdx.x; e < 256 * TILE; e += 512) {
            int b = e & (TILE - 1);
            int t = e >> LOG2TILE;
            int q = t & ((1 << slog) - 1);
            int p = t >> slog;
            float2 a = src[(q + ((p      ) << slog)) * TILE + b];
            float2 bb= src[(q + ((p +  m ) << slog)) * TILE + b];
            float2 c = src[(q + ((p + 2*m) << slog)) * TILE + b];
            float2 d = src[(q + ((p + 3*m) << slog)) * TILE + b];
            float2 w1 = twid(th0 * (float)p);
            float2 w2 = cmul(w1, w1), w3 = cmul(w2, w1);
            float2 e0, e1, e2, e3;
            r4core(a, bb, c, d, e0, e1, e2, e3);
            int base = q + ((4 * p) << slog);
            int s = 1 << slog;
            dst[(base        ) * TILE + b] = e0;
            dst[(base +     s) * TILE + b] = cmul(w1, e1);
            dst[(base + 2 * s) * TILE + b] = cmul(w2, e2);
            dst[(base + 3 * s) * TILE + b] = cmul(w3, e3);
        }
        __syncthreads();
        float2* tmp = src; src = dst; dst = tmp;
    }
    // after 3 swaps src == bB

    // stage 4: n_cur=4, s=256, p=0; gmem store natural order + optional max
    float localmax = 0.0f;
    {
        #pragma unroll
        for (int e = threadIdx.x; e < 256 * TILE; e += 512) {
            int b = e & (TILE - 1);
            int q = e >> LOG2TILE;
            float2 a = src[(q      ) * TILE + b];
            float2 bb= src[(q + 256) * TILE + b];
            float2 c = src[(q + 512) * TILE + b];
            float2 d = src[(q + 768) * TILE + b];
            float2 e0, e1, e2, e3;
            r4core(a, bb, c, d, e0, e1, e2, e3);
            int kc = k20 + b;
            int k0 = kc + ((q      ) << LOG2N2);
            int k1 = kc + ((q + 256) << LOG2N2);
            int k2 = kc + ((q + 512) << LOG2N2);
            int k3 = kc + ((q + 768) << LOG2N2);
            out[k0] = e0; out[k1] = e1; out[k2] = e2; out[k3] = e3;
            if (doMax) {
                if (k0 >= lo && k0 < hi) localmax = fmaxf(localmax, fabsf(e0.x));
                if (k1 >= lo && k1 < hi) localmax = fmaxf(localmax, fabsf(e1.x));
                if (k2 >= lo && k2 < hi) localmax = fmaxf(localmax, fabsf(e2.x));
                if (k3 >= lo && k3 < hi) localmax = fmaxf(localmax, fabsf(e3.x));
            }
        }
    }
    if (doMax) {
        #pragma unroll
        for (int off = 16; off > 0; off >>= 1)
            localmax = fmaxf(localmax, __shfl_xor_sync(0xffffffffu, localmax, off));
        __shared__ float wmax[16];
        int lane = threadIdx.x & 31, w = threadIdx.x >> 5;
        if (lane == 0) wmax[w] = localmax;
        __syncthreads();
        if (threadIdx.x == 0) {
            float mx = wmax[0];
            #pragma unroll
            for (int j = 1; j < 16; j++) mx = fmaxf(mx, wmax[j]);
            atomicMax(&g_max_bits, __float_as_uint(mx));   // values >= 0
        }
    }
}

// ---------------- specmul: unpack packed real-pair spectrum, multiply, conj,
// write transposed W[n1*N2+n2] = Yc[n1 + N1*n2]
__global__ void specmul_t(const float2* __restrict__ Z, float2* __restrict__ W) {
    __shared__ float2 tile[32][33];
    int n2_0 = blockIdx.x * 32;
    int n1_0 = blockIdx.y * 32;
    int tx = threadIdx.x;
    #pragma unroll
    for (int r = 0; r < 4; r++) {
        int ty = threadIdx.y + r * 8;
        int i = (n1_0 + tx) + ((n2_0 + ty) << LOG2N1);
        float2 zk = Z[i];
        float2 zn = Z[(NFFT - i) & (NFFT - 1)];
        float2 A  = make_float2(0.5f * (zk.x + zn.x), 0.5f * (zk.y - zn.y));
        float2 Dv = make_float2(zk.x - zn.x, zk.y + zn.y);
        float2 H  = make_float2(0.5f * Dv.y, -0.5f * Dv.x);
        float2 Y  = cmul(A, H);
        tile[ty][tx] = make_float2(Y.x, -Y.y);
    }
    __syncthreads();
    #pragma unroll
    for (int r = 0; r < 4; r++) {
        int ty = threadIdx.y + r * 8;
        W[((size_t)(n1_0 + ty) << LOG2N2) + n2_0 + tx] = tile[tx][ty];
    }
}

// ---------------- final: out[i] = W[M-1+i].x / max  (1/NFFT scale cancels)
__global__ void final_kernel(const float2* __restrict__ W,
                             float* __restrict__ out, int N, int M) {
    int i = blockIdx.x * blockDim.x + threadIdx.x;
    if (i < N) {
        float mx = __uint_as_float(g_max_bits);
        out[i] = W[(M - 1) + i].x / mx;
    }
}

extern "C" void kernel_launch(void* const* d_in, const int* in_sizes, int n_in,
                              void* d_out, int out_size) {
    const float* audio = (const float*)d_in[0];
    const float* ir    = (const float*)d_in[1];
    const int N = in_sizes[0];
    const int M = in_sizes[1];
    float* out = (float*)d_out;

    float2 *A = nullptr, *B = nullptr;
    cudaGetSymbolAddress((void**)&A, g_bufA);
    cudaGetSymbolAddress((void**)&B, g_bufB);

    cudaFuncSetAttribute(fft_rows, cudaFuncAttributeMaxDynamicSharedMemorySize, 2 * N2 * (int)sizeof(float2));
    cudaFuncSetAttribute(fft_cols, cudaFuncAttributeMaxDynamicSharedMemorySize, 2 * N1 * TILE * (int)sizeof(float2));

    dim3 tblk(32, 8);
    dim3 tgrid(N2 / 32, N1 / 32);

    pack_kernel<<<tgrid, tblk>>>(audio, N, ir, M, A);

    fft_rows<<<N1, 512, 2 * N2 * sizeof(float2)>>>(A, B);
    fft_cols<<<N2 / TILE, 512, 2 * N1 * TILE * sizeof(float2)>>>(B, A, 0, 0, 0);

    specmul_t<<<tgrid, tblk>>>(A, B);

    fft_rows<<<N1, 512, 2 * N2 * sizeof(float2)>>>(B, A);
    fft_cols<<<N2 / TILE, 512, 2 * N1 * TILE * sizeof(float2)>>>(A, B, 1, M - 1, M - 1 + N);

    final_kernel<<<(N + 255) / 256, 256>>>(B, out, N, M);
}

// round 4
// speedup vs baseline: 2.2979x; 1.1318x over previous
#include <cuda_runtime.h>

// Reverb via four-step FFT convolution. NFFT = 2^22 = N1*N2 (1024 x 4096).
// Radix-16 register FFTs (3 smem phases per 4096-pt FFT), conjugate-pair
// spectral multiply (half the reads), real-only windowed inverse output.

#define NFFT   (1 << 22)
#define N1     1024
#define N2     4096
#define LOG2N1 10
#define LOG2N2 12
#define TILE   4
#define SMPAD  4224          // SW(4095)=4222 < 4224

__device__ float2 g_bufA[NFFT];
__device__ float2 g_bufB[NFFT];
__device__ unsigned int g_max_bits;

__device__ __forceinline__ float2 cmul(float2 a, float2 b) {
    return make_float2(fmaf(a.x, b.x, -(a.y * b.y)),
                       fmaf(a.x, b.y,  (a.y * b.x)));
}
__device__ __forceinline__ float2 twid(float ang) {   // e^{-i ang}
    float sn, cs; __sincosf(ang, &sn, &cs);
    return make_float2(cs, -sn);
}
__device__ __forceinline__ int SW(int x) { return x + (x >> 5); }

// radix-4 DFT core (omega4 = e^{-i pi/2})
__device__ __forceinline__ void r4core(float2 a, float2 b, float2 c, float2 d,
                                       float2& e0, float2& e1, float2& e2, float2& e3) {
    float2 apc = make_float2(a.x + c.x, a.y + c.y);
    float2 amc = make_float2(a.x - c.x, a.y - c.y);
    float2 bpd = make_float2(b.x + d.x, b.y + d.y);
    float2 bmd = make_float2(b.x - d.x, b.y - d.y);
    e0 = make_float2(apc.x + bpd.x, apc.y + bpd.y);
    e1 = make_float2(amc.x + bmd.y, amc.y - bmd.x);
    e2 = make_float2(apc.x - bpd.x, apc.y - bpd.y);
    e3 = make_float2(amc.x - bmd.y, amc.y + bmd.x);
}

// 16-point DFT: X[r] = sum_u x[u] w16^{ru}. u = u0 + 4u1; two radix-4 layers.
__device__ __forceinline__ void dft16(const float2* x, float2* X) {
    const float C1 = 0.92387953251128675613f;
    const float S1 = 0.38268343236508977173f;
    const float R2 = 0.70710678118654752440f;
    float2 t0[4], t1[4], t2[4], t3[4];
    r4core(x[0], x[4], x[8],  x[12], t0[0], t0[1], t0[2], t0[3]);
    r4core(x[1], x[5], x[9],  x[13], t1[0], t1[1], t1[2], t1[3]);
    r4core(x[2], x[6], x[10], x[14], t2[0], t2[1], t2[2], t2[3]);
    r4core(x[3], x[7], x[11], x[15], t3[0], t3[1], t3[2], t3[3]);
    // omega16^{u0*r0}
    t1[1] = cmul(t1[1], make_float2( C1, -S1));
    t1[2] = cmul(t1[2], make_float2( R2, -R2));
    t1[3] = cmul(t1[3], make_float2( S1, -C1));
    t2[1] = cmul(t2[1], make_float2( R2, -R2));
    t2[2] = make_float2(t2[2].y, -t2[2].x);           // * (0,-1)
    t2[3] = cmul(t2[3], make_float2(-R2, -R2));
    t3[1] = cmul(t3[1], make_float2( S1, -C1));
    t3[2] = cmul(t3[2], make_float2(-R2, -R2));
    t3[3] = cmul(t3[3], make_float2(-C1,  S1));
    r4core(t0[0], t1[0], t2[0], t3[0], X[0], X[4], X[8],  X[12]);
    r4core(t0[1], t1[1], t2[1], t3[1], X[1], X[5], X[9],  X[13]);
    r4core(t0[2], t1[2], t2[2], t3[2], X[2], X[6], X[10], X[14]);
    r4core(t0[3], t1[3], t2[3], t3[3], X[3], X[7], X[11], X[15]);
}

// ---------------- pack: z = audio + i*flip(ir), transposed G0[n1*N2+n2]
__global__ void pack_kernel(const float* __restrict__ audio, int N,
                            const float* __restrict__ ir, int M,
                            float2* __restrict__ G0) {
    __shared__ float2 tile[32][33];
    if (blockIdx.x == 0 && blockIdx.y == 0 && threadIdx.x == 0 && threadIdx.y == 0)
        g_max_bits = 0u;
    int n2_0 = blockIdx.x * 32;
    int n1_0 = blockIdx.y * 32;
    int tx = threadIdx.x;
    #pragma unroll
    for (int r = 0; r < 4; r++) {
        int ty = threadIdx.y + r * 8;
        int i = (n1_0 + tx) + ((n2_0 + ty) << LOG2N1);
        float re = (i < N) ? audio[i] : 0.0f;
        float im = (i < M) ? ir[M - 1 - i] : 0.0f;
        tile[ty][tx] = make_float2(re, im);
    }
    __syncthreads();
    #pragma unroll
    for (int r = 0; r < 4; r++) {
        int ty = threadIdx.y + r * 8;
        G0[((size_t)(n1_0 + ty) << LOG2N2) + n2_0 + tx] = tile[tx][ty];
    }
}

// ---------------- fft_rows16: 4096-pt FFT = 3 radix-16 stages. 256 threads.
// Inter-dimension twiddle e^{-2pi i n1 k / NFFT} fused into stage 3 (p=0 there).
__global__ void fft_rows16(const float2* __restrict__ in, float2* __restrict__ out) {
    extern __shared__ float2 sm[];
    float2* bA = sm;
    float2* bB = sm + SMPAD;
    int n1 = blockIdx.x;
    int t = threadIdx.x;
    const float2* row = in + ((size_t)n1 << LOG2N2);
    float2* orow = out + ((size_t)n1 << LOG2N2);
    float2 x[16], X[16];

    // stage 1: n=4096, s=1, p=t
    #pragma unroll
    for (int u = 0; u < 16; u++) x[u] = row[t + (u << 8)];
    dft16(x, X);
    {
        float2 w1 = twid((6.2831853071795865f / 4096.0f) * (float)t);
        float2 cur = make_float2(1.0f, 0.0f);
        #pragma unroll
        for (int r = 0; r < 16; r++) { bA[SW(16 * t + r)] = cmul(X[r], cur); cur = cmul(cur, w1); }
    }
    __syncthreads();

    // stage 2: n=256, s=16, q=t&15, p=t>>4
    #pragma unroll
    for (int u = 0; u < 16; u++) x[u] = bA[SW(t + (u << 8))];
    dft16(x, X);
    {
        int q = t & 15, p = t >> 4;
        float2 w1 = twid((6.2831853071795865f / 256.0f) * (float)p);
        float2 cur = make_float2(1.0f, 0.0f);
        int base = q + (p << 8);
        #pragma unroll
        for (int r = 0; r < 16; r++) { bB[SW(base + 16 * r)] = cmul(X[r], cur); cur = cmul(cur, w1); }
    }
    __syncthreads();

    // stage 3: n=16, s=256, p=0 (trivial stage twiddle) + interdim twiddle + store
    #pragma unroll
    for (int u = 0; u < 16; u++) x[u] = bB[SW(t + (u << 8))];
    dft16(x, X);
    {
        const float c0 = 6.2831853071795865f / (float)NFFT;
        float2 cur = twid(c0 * (float)(n1 * t));          // n1*t < 2^18, exact
        float2 V   = twid(c0 * (float)(n1 << 8));
        #pragma unroll
        for (int r = 0; r < 16; r++) { orow[t + (r << 8)] = cmul(X[r], cur); cur = cmul(cur, V); }
    }
}

// ---------------- fft_cols16: 1024-pt FFTs over TILE=4 columns. 256 threads.
// Stages: radix-16 (n=1024,s=1), radix-16 (n=64,s=16), radix-4 (n=4,s=256,p=0).
// doMax=0: write complex natural order. doMax=1: write real part only in
// window [lo,hi) to outr and reduce max|.|.
__global__ void fft_cols16(const float2* __restrict__ in,
                           float2* __restrict__ outc, float* __restrict__ outr,
                           int doMax, int lo, int hi) {
    extern __shared__ float2 sm[];
    float2* bA = sm;
    float2* bB = sm + SMPAD;
    int k20 = blockIdx.x * TILE;
    int t = threadIdx.x;
    int b = t & 3, tt = t >> 2;      // tt in [0,64)
    float2 x[16], X[16];

    // stage 1: p=tt
    #pragma unroll
    for (int u = 0; u < 16; u++)
        x[u] = in[((size_t)(tt + (u << 6)) << LOG2N2) + k20 + b];
    dft16(x, X);
    {
        float2 w1 = twid((6.2831853071795865f / 1024.0f) * (float)tt);
        float2 cur = make_float2(1.0f, 0.0f);
        #pragma unroll
        for (int r = 0; r < 16; r++) {
            bA[SW(((16 * tt + r) << 2) + b)] = cmul(X[r], cur); cur = cmul(cur, w1);
        }
    }
    __syncthreads();

    // stage 2: q=tt&15, p=tt>>4 (in [0,4))
    #pragma unroll
    for (int u = 0; u < 16; u++) x[u] = bA[SW(((tt + (u << 6)) << 2) + b)];
    dft16(x, X);
    {
        int q = tt & 15, p = tt >> 4;
        float2 w1 = twid((6.2831853071795865f / 64.0f) * (float)p);
        float2 cur = make_float2(1.0f, 0.0f);
        int base = q + (p << 8);
        #pragma unroll
        for (int r = 0; r < 16; r++) {
            bB[SW(((base + 16 * r) << 2) + b)] = cmul(X[r], cur); cur = cmul(cur, w1);
        }
    }
    __syncthreads();

    // stage 3: radix-4, p=0; 4 butterflies per thread; fused gmem epilogue
    float lmax = 0.0f;
    unsigned wlen = (unsigned)(hi - lo);
    #pragma unroll
    for (int v = 0; v < 4; v++) {
        int q = tt + (v << 6);
        float2 a  = bB[SW(((q      ) << 2) + b)];
        float2 bb = bB[SW(((q + 256) << 2) + b)];
        float2 c  = bB[SW(((q + 512) << 2) + b)];
        float2 d  = bB[SW(((q + 768) << 2) + b)];
        float2 e0, e1, e2, e3;
        r4core(a, bb, c, d, e0, e1, e2, e3);
        int kc = k20 + b;
        int k0 = kc + ((q      ) << LOG2N2);
        int k1 = kc + ((q + 256) << LOG2N2);
        int k2 = kc + ((q + 512) << LOG2N2);
        int k3 = kc + ((q + 768) << LOG2N2);
        if (!doMax) {
            outc[k0] = e0; outc[k1] = e1; outc[k2] = e2; outc[k3] = e3;
        } else {
            if ((unsigned)(k0 - lo) < wlen) { outr[k0] = e0.x; lmax = fmaxf(lmax, fabsf(e0.x)); }
            if ((unsigned)(k1 - lo) < wlen) { outr[k1] = e1.x; lmax = fmaxf(lmax, fabsf(e1.x)); }
            if ((unsigned)(k2 - lo) < wlen) { outr[k2] = e2.x; lmax = fmaxf(lmax, fabsf(e2.x)); }
            if ((unsigned)(k3 - lo) < wlen) { outr[k3] = e3.x; lmax = fmaxf(lmax, fabsf(e3.x)); }
        }
    }
    if (doMax) {
        #pragma unroll
        for (int off = 16; off > 0; off >>= 1)
            lmax = fmaxf(lmax, __shfl_xor_sync(0xffffffffu, lmax, off));
        __shared__ float wmax[8];
        int lane = t & 31, w = t >> 5;
        if (lane == 0) wmax[w] = lmax;
        __syncthreads();
        if (t == 0) {
            float mx = wmax[0];
            #pragma unroll
            for (int j = 1; j < 8; j++) mx = fmaxf(mx, wmax[j]);
            atomicMax(&g_max_bits, __float_as_uint(mx));   // values >= 0
        }
    }
}

// ---------------- specmul (conjugate-pair): process i=(n1,n2) and its mirror
// j = N-i = (N1-n1, N2-1-n2) for n1 in [1,511]. W(i)=conj(Y), W(j)=Y.
// Rows 0 and 512 handled by specmul_pairB (which overwrites row 0 garbage).
__global__ void specmul_pairA(const float2* __restrict__ Z, float2* __restrict__ W) {
    __shared__ float2 tC[32][33];
    __shared__ float2 tM[32][33];
    int n2_0 = blockIdx.x * 32;       // 128 tiles (full n2 range)
    int n1_0 = blockIdx.y * 32;       // 16 tiles (n1 in [0,512))
    int tx = threadIdx.x;
    int n1 = n1_0 + tx;
    #pragma unroll
    for (int r = 0; r < 4; r++) {
        int ty = threadIdx.y + (r << 3);
        int n2 = n2_0 + ty;
        if (n1 != 0) {
            float2 zk = Z[n1 + (n2 << LOG2N1)];
            float2 zn = Z[(N1 - n1) + ((N2 - 1 - n2) << LOG2N1)];
            float2 A  = make_float2(0.5f * (zk.x + zn.x), 0.5f * (zk.y - zn.y));
            float2 Dv = make_float2(zk.x - zn.x, zk.y + zn.y);
            float2 H  = make_float2(0.5f * Dv.y, -0.5f * Dv.x);
            float2 Y  = cmul(A, H);
            tC[ty][tx] = make_float2(Y.x, -Y.y);
            tM[ty][tx] = Y;
        }
    }
    __syncthreads();
    #pragma unroll
    for (int r = 0; r < 4; r++) {
        int ty = threadIdx.y + (r << 3);
        int row = n1_0 + ty;
        W[(size_t)row * N2 + n2_0 + tx] = tC[tx][ty];      // row 0: garbage, fixed by B
        int rm = N1 - row;
        if (rm < N1)
            W[(size_t)rm * N2 + (N2 - 1 - (n2_0 + tx))] = tM[tx][ty];
    }
}

__global__ void specmul_pairB(const float2* __restrict__ Z, float2* __restrict__ W) {
    int tid = blockIdx.x * blockDim.x + threadIdx.x;
    if (tid <= 2048) {                       // row 0 line: i = N1*n2
        int n2 = tid;
        int j2 = (N2 - n2) & (N2 - 1);
        float2 zk = Z[(size_t)n2 << LOG2N1];
        float2 zn = Z[(size_t)j2 << LOG2N1];
        float2 A  = make_float2(0.5f * (zk.x + zn.x), 0.5f * (zk.y - zn.y));
        float2 Dv = make_float2(zk.x - zn.x, zk.y + zn.y);
        float2 H  = make_float2(0.5f * Dv.y, -0.5f * Dv.x);
        float2 Y  = cmul(A, H);
        W[n2] = make_float2(Y.x, -Y.y);
        W[j2] = Y;
    } else if (tid < 2049 + 2048) {          // row 512 line: i = 512 + N1*n2
        int n2 = tid - 2049;                 // [0,2048)
        float2 zk = Z[512 + (n2 << LOG2N1)];
        float2 zn = Z[512 + ((N2 - 1 - n2) << LOG2N1)];
        float2 A  = make_float2(0.5f * (zk.x + zn.x), 0.5f * (zk.y - zn.y));
        float2 Dv = make_float2(zk.x - zn.x, zk.y + zn.y);
        float2 H  = make_float2(0.5f * Dv.y, -0.5f * Dv.x);
        float2 Y  = cmul(A, H);
        W[(size_t)512 * N2 + n2]            = make_float2(Y.x, -Y.y);
        W[(size_t)512 * N2 + (N2 - 1 - n2)] = Y;
    }
}

// ---------------- final: out[i] = y[M-1+i] / max  (1/NFFT scale cancels)
__global__ void final_kernel(const float* __restrict__ yf,
                             float* __restrict__ out, int N, int M) {
    int i = blockIdx.x * blockDim.x + threadIdx.x;
    if (i < N) {
        float mx = __uint_as_float(g_max_bits);
        out[i] = yf[(M - 1) + i] / mx;
    }
}

extern "C" void kernel_launch(void* const* d_in, const int* in_sizes, int n_in,
                              void* d_out, int out_size) {
    const float* audio = (const float*)d_in[0];
    const float* ir    = (const float*)d_in[1];
    const int N = in_sizes[0];
    const int M = in_sizes[1];
    float* out = (float*)d_out;

    float2 *A = nullptr, *B = nullptr;
    cudaGetSymbolAddress((void**)&A, g_bufA);
    cudaGetSymbolAddress((void**)&B, g_bufB);

    const int SMEM = 2 * SMPAD * (int)sizeof(float2);   // 67584 B
    cudaFuncSetAttribute(fft_rows16, cudaFuncAttributeMaxDynamicSharedMemorySize, SMEM);
    cudaFuncSetAttribute(fft_cols16, cudaFuncAttributeMaxDynamicSharedMemorySize, SMEM);

    dim3 tblk(32, 8);

    // pack (transpose): -> A
    pack_kernel<<<dim3(N2 / 32, N1 / 32), tblk>>>(audio, N, ir, M, A);

    // forward FFT: rows A->B, cols B->A (natural-order spectrum Z in A)
    fft_rows16<<<N1, 256, SMEM>>>(A, B);
    fft_cols16<<<N2 / TILE, 256, SMEM>>>(B, A, nullptr, 0, 0, 0);

    // spectral multiply (paired) + conj + transpose: A -> B
    specmul_pairA<<<dim3(N2 / 32, 16), tblk>>>(A, B);
    specmul_pairB<<<17, 256>>>(A, B);

    // inverse (forward of conj): rows B->A, cols A-> real y in (float*)B
    fft_rows16<<<N1, 256, SMEM>>>(B, A);
    fft_cols16<<<N2 / TILE, 256, SMEM>>>(A, nullptr, (float*)B, 1, M - 1, M - 1 + N);

    final_kernel<<<(N + 255) / 256, 256>>>((const float*)B, out, N, M);
}

// round 5
// speedup vs baseline: 2.9518x; 1.2846x over previous
#include <cuda_runtime.h>

// Reverb via four-step FFT convolution, NFFT = 3*2^20 = 3,145,728 = N1*N2,
// N1 = 768 (16*16*3), N2 = 4096 (16*16*16).  NFFT >= N + 2(M-1) = 3,086,998.
//   y[i] = sum_j audio[i+j]*ir[j],  out = y / max|y|
// Forward FFT of z = audio + i*flip(ir), conjugate-pair spectral multiply,
// forward FFT of conj = inverse, windowed real output + fused max reduction.

#define NFFT   3145728
#define N1     768
#define N2     4096
#define TILE   8
#define LOG2TILE 3
#define SMPAD_R  4224      // rows: SW(4095) = 4222
#define SMPAD_C  6336      // cols: SW(768*8-1) = 6334

__device__ float2 g_bufA[1 << 22];
__device__ float2 g_bufB[1 << 22];
__device__ unsigned int g_max_bits;

__device__ __forceinline__ float2 cmul(float2 a, float2 b) {
    return make_float2(fmaf(a.x, b.x, -(a.y * b.y)),
                       fmaf(a.x, b.y,  (a.y * b.x)));
}
__device__ __forceinline__ float2 twid(float ang) {   // e^{-i ang}
    float sn, cs; __sincosf(ang, &sn, &cs);
    return make_float2(cs, -sn);
}
__device__ __forceinline__ int SW(int x) { return x + (x >> 5); }

__device__ __forceinline__ void r4core(float2 a, float2 b, float2 c, float2 d,
                                       float2& e0, float2& e1, float2& e2, float2& e3) {
    float2 apc = make_float2(a.x + c.x, a.y + c.y);
    float2 amc = make_float2(a.x - c.x, a.y - c.y);
    float2 bpd = make_float2(b.x + d.x, b.y + d.y);
    float2 bmd = make_float2(b.x - d.x, b.y - d.y);
    e0 = make_float2(apc.x + bpd.x, apc.y + bpd.y);
    e1 = make_float2(amc.x + bmd.y, amc.y - bmd.x);
    e2 = make_float2(apc.x - bpd.x, apc.y - bpd.y);
    e3 = make_float2(amc.x - bmd.y, amc.y + bmd.x);
}

// 16-point DFT (two radix-4 layers, constant omega16 twiddles)
__device__ __forceinline__ void dft16(const float2* x, float2* X) {
    const float C1 = 0.92387953251128675613f;
    const float S1 = 0.38268343236508977173f;
    const float R2 = 0.70710678118654752440f;
    float2 t0[4], t1[4], t2[4], t3[4];
    r4core(x[0], x[4], x[8],  x[12], t0[0], t0[1], t0[2], t0[3]);
    r4core(x[1], x[5], x[9],  x[13], t1[0], t1[1], t1[2], t1[3]);
    r4core(x[2], x[6], x[10], x[14], t2[0], t2[1], t2[2], t2[3]);
    r4core(x[3], x[7], x[11], x[15], t3[0], t3[1], t3[2], t3[3]);
    t1[1] = cmul(t1[1], make_float2( C1, -S1));
    t1[2] = cmul(t1[2], make_float2( R2, -R2));
    t1[3] = cmul(t1[3], make_float2( S1, -C1));
    t2[1] = cmul(t2[1], make_float2( R2, -R2));
    t2[2] = make_float2(t2[2].y, -t2[2].x);
    t2[3] = cmul(t2[3], make_float2(-R2, -R2));
    t3[1] = cmul(t3[1], make_float2( S1, -C1));
    t3[2] = cmul(t3[2], make_float2(-R2, -R2));
    t3[3] = cmul(t3[3], make_float2(-C1,  S1));
    r4core(t0[0], t1[0], t2[0], t3[0], X[0], X[4], X[8],  X[12]);
    r4core(t0[1], t1[1], t2[1], t3[1], X[1], X[5], X[9],  X[13]);
    r4core(t0[2], t1[2], t2[2], t3[2], X[2], X[6], X[10], X[14]);
    r4core(t0[3], t1[3], t2[3], t3[3], X[3], X[7], X[11], X[15]);
}

// ---------------- pack: z = audio + i*flip(ir), transposed G0[n1*N2 + n2]
__global__ void pack_kernel(const float* __restrict__ audio, int N,
                            const float* __restrict__ ir, int M,
                            float2* __restrict__ G0) {
    __shared__ float2 tile[32][33];
    if (blockIdx.x == 0 && blockIdx.y == 0 && threadIdx.x == 0 && threadIdx.y == 0)
        g_max_bits = 0u;
    int n2_0 = blockIdx.x * 32;
    int n1_0 = blockIdx.y * 32;
    int tx = threadIdx.x;
    #pragma unroll
    for (int r = 0; r < 4; r++) {
        int ty = threadIdx.y + (r << 3);
        int i = (n1_0 + tx) + N1 * (n2_0 + ty);
        float re = (i < N) ? audio[i] : 0.0f;
        float im = (i < M) ? ir[M - 1 - i] : 0.0f;
        tile[ty][tx] = make_float2(re, im);
    }
    __syncthreads();
    #pragma unroll
    for (int r = 0; r < 4; r++) {
        int ty = threadIdx.y + (r << 3);
        G0[(size_t)(n1_0 + ty) * N2 + n2_0 + tx] = tile[tx][ty];
    }
}

// ---------------- fft_rows16: 4096-pt FFT per row, 256 threads, 3 radix-16
// stages; inter-dim twiddle e^{-2pi i n1 k2 / NFFT} fused into stage 3 (p=0).
__global__ void fft_rows16(const float2* __restrict__ in, float2* __restrict__ out) {
    extern __shared__ float2 sm[];
    float2* bA = sm;
    float2* bB = sm + SMPAD_R;
    int n1 = blockIdx.x;
    int t = threadIdx.x;
    const float2* row = in + (size_t)n1 * N2;
    float2* orow = out + (size_t)n1 * N2;
    float2 x[16], X[16];

    // stage 1: n=4096, s=1, p=t
    #pragma unroll
    for (int u = 0; u < 16; u++) x[u] = row[t + (u << 8)];
    dft16(x, X);
    {
        float2 w1 = twid((6.2831853071795865f / 4096.0f) * (float)t);
        float2 cur = make_float2(1.0f, 0.0f);
        #pragma unroll
        for (int r = 0; r < 16; r++) { bA[SW(16 * t + r)] = cmul(X[r], cur); cur = cmul(cur, w1); }
    }
    __syncthreads();

    // stage 2: n=256, s=16
    #pragma unroll
    for (int u = 0; u < 16; u++) x[u] = bA[SW(t + (u << 8))];
    dft16(x, X);
    {
        int q = t & 15, p = t >> 4;
        float2 w1 = twid((6.2831853071795865f / 256.0f) * (float)p);
        float2 cur = make_float2(1.0f, 0.0f);
        int base = q + (p << 8);
        #pragma unroll
        for (int r = 0; r < 16; r++) { bB[SW(base + 16 * r)] = cmul(X[r], cur); cur = cmul(cur, w1); }
    }
    __syncthreads();

    // stage 3: n=16, s=256, p=0; fused inter-dim twiddle + store
    #pragma unroll
    for (int u = 0; u < 16; u++) x[u] = bB[SW(t + (u << 8))];
    dft16(x, X);
    {
        const float c0 = 6.2831853071795865f / (float)NFFT;
        // n1*k2 <= 767*4095 < NFFT and < 2^24: float-exact, no modulo needed
        float2 cur = twid(c0 * (float)(n1 * t));
        float2 V   = twid(c0 * (float)(n1 << 8));
        #pragma unroll
        for (int r = 0; r < 16; r++) { orow[t + (r << 8)] = cmul(X[r], cur); cur = cmul(cur, V); }
    }
}

// ---------------- fft_cols768: 768-pt FFTs (16*16*3) over TILE=8 columns.
// 384 threads. Stage 3 is radix-3 with p=0 (twiddle-free), fused with the
// gmem epilogue: complex natural order (fwd) or windowed real + max (inv).
__global__ void fft_cols768(const float2* __restrict__ in,
                            float2* __restrict__ outc, float* __restrict__ outr,
                            int doMax, int lo, int hi) {
    extern __shared__ float2 sm[];
    float2* bA = sm;
    float2* bB = sm + SMPAD_C;
    int k20 = blockIdx.x * TILE;
    int t = threadIdx.x;
    int b = t & (TILE - 1), tt = t >> LOG2TILE;    // tt in [0,48)
    float2 x[16], X[16];

    // stage 1: n=768, s=1, m=48, p=tt
    #pragma unroll
    for (int u = 0; u < 16; u++)
        x[u] = in[(size_t)(tt + 48 * u) * N2 + k20 + b];
    dft16(x, X);
    {
        float2 w1 = twid((6.2831853071795865f / 768.0f) * (float)tt);
        float2 cur = make_float2(1.0f, 0.0f);
        #pragma unroll
        for (int r = 0; r < 16; r++) {
            bA[SW(((16 * tt + r) << LOG2TILE) + b)] = cmul(X[r], cur); cur = cmul(cur, w1);
        }
    }
    __syncthreads();

    // stage 2: n=48, s=16, m=3; q=tt&15, p=tt>>4 (in [0,3))
    #pragma unroll
    for (int u = 0; u < 16; u++) x[u] = bA[SW(((tt + 48 * u) << LOG2TILE) + b)];
    dft16(x, X);
    {
        int q = tt & 15, p = tt >> 4;
        float2 w1 = twid((6.2831853071795865f / 48.0f) * (float)p);
        float2 cur = make_float2(1.0f, 0.0f);
        int base = q + (p << 8);
        #pragma unroll
        for (int r = 0; r < 16; r++) {
            bB[SW(((base + 16 * r) << LOG2TILE) + b)] = cmul(X[r], cur); cur = cmul(cur, w1);
        }
    }
    __syncthreads();

    // stage 3: radix-3, s=256, p=0; outputs k1 = q + 256r
    const float SQ32 = 0.86602540378443864676f;
    float lmax = 0.0f;
    unsigned wlen = (unsigned)(hi - lo);
    for (int q = tt; q < 256; q += 48) {
        float2 a  = bB[SW(((q      ) << LOG2TILE) + b)];
        float2 bb = bB[SW(((q + 256) << LOG2TILE) + b)];
        float2 c  = bB[SW(((q + 512) << LOG2TILE) + b)];
        float2 ts = make_float2(bb.x + c.x, bb.y + c.y);
        float2 u  = make_float2(bb.x - c.x, bb.y - c.y);
        float2 e0 = make_float2(a.x + ts.x, a.y + ts.y);
        float rx = a.x - 0.5f * ts.x, ry = a.y - 0.5f * ts.y;
        float2 e1 = make_float2(rx + SQ32 * u.y, ry - SQ32 * u.x);
        float2 e2 = make_float2(rx - SQ32 * u.y, ry + SQ32 * u.x);
        int kc = k20 + b;
        int k0 = kc + ((q      ) << 12);
        int k1 = kc + ((q + 256) << 12);
        int k2 = kc + ((q + 512) << 12);
        if (!doMax) {
            outc[k0] = e0; outc[k1] = e1; outc[k2] = e2;
        } else {
            if ((unsigned)(k0 - lo) < wlen) { outr[k0] = e0.x; lmax = fmaxf(lmax, fabsf(e0.x)); }
            if ((unsigned)(k1 - lo) < wlen) { outr[k1] = e1.x; lmax = fmaxf(lmax, fabsf(e1.x)); }
            if ((unsigned)(k2 - lo) < wlen) { outr[k2] = e2.x; lmax = fmaxf(lmax, fabsf(e2.x)); }
        }
    }
    if (doMax) {
        #pragma unroll
        for (int off = 16; off > 0; off >>= 1)
            lmax = fmaxf(lmax, __shfl_xor_sync(0xffffffffu, lmax, off));
        __shared__ float wmax[12];
        int lane = t & 31, w = t >> 5;
        if (lane == 0) wmax[w] = lmax;
        __syncthreads();
        if (t == 0) {
            float mx = wmax[0];
            #pragma unroll
            for (int j = 1; j < 12; j++) mx = fmaxf(mx, wmax[j]);
            atomicMax(&g_max_bits, __float_as_uint(mx));   // values >= 0
        }
    }
}

// ---------------- specmul (conjugate pairs): k = n1 + N1*n2; mirror of
// (n1,n2) is (N1-n1, N2-1-n2) for n1 in [1,N1). Rows 0, 384 via pairB.
// W(i) = conj(Y(i)) stored transposed W[n1*N2 + n2]; W(mirror) = Y.
__global__ void specmul_pairA(const float2* __restrict__ Z, float2* __restrict__ W) {
    __shared__ float2 tC[32][33];
    __shared__ float2 tM[32][33];
    int n2_0 = blockIdx.x * 32;       // 128 tiles
    int n1_0 = blockIdx.y * 32;       // 12 tiles: n1 in [0,384)
    int tx = threadIdx.x;
    int n1 = n1_0 + tx;
    #pragma unroll
    for (int r = 0; r < 4; r++) {
        int ty = threadIdx.y + (r << 3);
        int n2 = n2_0 + ty;
        if (n1 != 0) {
            float2 zk = Z[n1 + N1 * n2];
            float2 zn = Z[(N1 - n1) + N1 * (N2 - 1 - n2)];
            float2 A  = make_float2(0.5f * (zk.x + zn.x), 0.5f * (zk.y - zn.y));
            float2 Dv = make_float2(zk.x - zn.x, zk.y + zn.y);
            float2 H  = make_float2(0.5f * Dv.y, -0.5f * Dv.x);
            float2 Y  = cmul(A, H);
            tC[ty][tx] = make_float2(Y.x, -Y.y);
            tM[ty][tx] = Y;
        }
    }
    __syncthreads();
    #pragma unroll
    for (int r = 0; r < 4; r++) {
        int ty = threadIdx.y + (r << 3);
        int row = n1_0 + ty;
        W[(size_t)row * N2 + n2_0 + tx] = tC[tx][ty];      // row 0 garbage -> pairB
        int rm = N1 - row;
        if (rm < N1)
            W[(size_t)rm * N2 + (N2 - 1 - (n2_0 + tx))] = tM[tx][ty];
    }
}

__global__ void specmul_pairB(const float2* __restrict__ Z, float2* __restrict__ W) {
    int tid = blockIdx.x * blockDim.x + threadIdx.x;
    if (tid <= 2048) {                        // row 0: k = N1*n2, mirror (0, (N2-n2)&)
        int n2 = tid;
        int j2 = (N2 - n2) & (N2 - 1);
        float2 zk = Z[(size_t)n2 * N1];
        float2 zn = Z[(size_t)j2 * N1];
        float2 A  = make_float2(0.5f * (zk.x + zn.x), 0.5f * (zk.y - zn.y));
        float2 Dv = make_float2(zk.x - zn.x, zk.y + zn.y);
        float2 H  = make_float2(0.5f * Dv.y, -0.5f * Dv.x);
        float2 Y  = cmul(A, H);
        W[n2] = make_float2(Y.x, -Y.y);
        W[j2] = Y;
    } else if (tid < 2049 + 2048) {           // row 384: mirror (384, N2-1-n2)
        int n2 = tid - 2049;
        float2 zk = Z[384 + N1 * n2];
        float2 zn = Z[384 + N1 * (N2 - 1 - n2)];
        float2 A  = make_float2(0.5f * (zk.x + zn.x), 0.5f * (zk.y - zn.y));
        float2 Dv = make_float2(zk.x - zn.x, zk.y + zn.y);
        float2 H  = make_float2(0.5f * Dv.y, -0.5f * Dv.x);
        float2 Y  = cmul(A, H);
        W[(size_t)384 * N2 + n2]            = make_float2(Y.x, -Y.y);
        W[(size_t)384 * N2 + (N2 - 1 - n2)] = Y;
    }
}

// ---------------- final: out[i] = y[M-1+i] / max
__global__ void final_kernel(const float* __restrict__ yf,
                             float* __restrict__ out, int N, int M) {
    int i = blockIdx.x * blockDim.x + threadIdx.x;
    if (i < N) {
        float mx = __uint_as_float(g_max_bits);
        out[i] = yf[(M - 1) + i] / mx;
    }
}

extern "C" void kernel_launch(void* const* d_in, const int* in_sizes, int n_in,
                              void* d_out, int out_size) {
    const float* audio = (const float*)d_in[0];
    const float* ir    = (const float*)d_in[1];
    const int N = in_sizes[0];
    const int M = in_sizes[1];
    float* out = (float*)d_out;

    float2 *A = nullptr, *B = nullptr;
    cudaGetSymbolAddress((void**)&A, g_bufA);
    cudaGetSymbolAddress((void**)&B, g_bufB);

    const int SMEM_R = 2 * SMPAD_R * (int)sizeof(float2);   // 67584
    const int SMEM_C = 2 * SMPAD_C * (int)sizeof(float2);   // 101376
    cudaFuncSetAttribute(fft_rows16, cudaFuncAttributeMaxDynamicSharedMemorySize, SMEM_R);
    cudaFuncSetAttribute(fft_cols768, cudaFuncAttributeMaxDynamicSharedMemorySize, SMEM_C);

    dim3 tblk(32, 8);

    pack_kernel<<<dim3(N2 / 32, N1 / 32), tblk>>>(audio, N, ir, M, A);

    // forward: rows A->B, cols B->A (natural-order spectrum Z in A)
    fft_rows16<<<N1, 256, SMEM_R>>>(A, B);
    fft_cols768<<<N2 / TILE, 384, SMEM_C>>>(B, A, nullptr, 0, 0, 0);

    // spectral multiply (paired) + conj + transpose: A -> B
    specmul_pairA<<<dim3(N2 / 32, 12), tblk>>>(A, B);
    specmul_pairB<<<17, 256>>>(A, B);

    // inverse: rows B->A, cols A-> windowed real y in (float*)B
    fft_rows16<<<N1, 256, SMEM_R>>>(B, A);
    fft_cols768<<<N2 / TILE, 384, SMEM_C>>>(A, nullptr, (float*)B, 1, M - 1, M - 1 + N);

    final_kernel<<<(N + 255) / 256, 256>>>((const float*)B, out, N, M);
}

// round 6
// speedup vs baseline: 3.4774x; 1.1780x over previous
#include <cuda_runtime.h>

// Reverb via four-step FFT convolution + half-size real inverse (C2R).
// NFFT = 3*2^20 = 3,145,728 = 768*4096 >= N + 2(M-1).  NH = NFFT/2 = 768*2048.
// Forward: z = audio + i*flip(ir), 4096-pt rows FFT, 768-pt cols FFT -> Z[k].
// specmul: unpack A,H from Z pairs, Y = A*H, then C2R split V[m] from
// (Y[m], Y[NH-m]); store conj(V) transposed for the half-size inverse.
// Inverse: 2048-pt rows FFT, 768-pt cols FFT; epilogue emits y[2m],y[2m+1]
// = (Re, -Im) of the forward-of-conj result, windowed, with fused max-abs.

#define NFFT   3145728
#define NH     1572864        // NFFT/2
#define N1     768
#define N2     4096
#define N2V    2048           // inverse row length
#define TILE   8
#define LOG2TILE 3
#define SMPAD_R  4224         // SW(4095)=4222
#define SMPAD_R2 2112         // SW(2047)=2110
#define SMPAD_C  6336         // SW(6143)=6334

__device__ float2 g_bufA[1 << 22];
__device__ float2 g_bufB[1 << 22];
__device__ unsigned int g_max_bits;

__device__ __forceinline__ float2 cmul(float2 a, float2 b) {
    return make_float2(fmaf(a.x, b.x, -(a.y * b.y)),
                       fmaf(a.x, b.y,  (a.y * b.x)));
}
__device__ __forceinline__ float2 twid(float ang) {   // e^{-i ang}
    float sn, cs; __sincosf(ang, &sn, &cs);
    return make_float2(cs, -sn);
}
__device__ __forceinline__ int SW(int x) { return x + (x >> 5); }

__device__ __forceinline__ void r4core(float2 a, float2 b, float2 c, float2 d,
                                       float2& e0, float2& e1, float2& e2, float2& e3) {
    float2 apc = make_float2(a.x + c.x, a.y + c.y);
    float2 amc = make_float2(a.x - c.x, a.y - c.y);
    float2 bpd = make_float2(b.x + d.x, b.y + d.y);
    float2 bmd = make_float2(b.x - d.x, b.y - d.y);
    e0 = make_float2(apc.x + bpd.x, apc.y + bpd.y);
    e1 = make_float2(amc.x + bmd.y, amc.y - bmd.x);
    e2 = make_float2(apc.x - bpd.x, apc.y - bpd.y);
    e3 = make_float2(amc.x - bmd.y, amc.y + bmd.x);
}

__device__ __forceinline__ void dft16(const float2* x, float2* X) {
    const float C1 = 0.92387953251128675613f;
    const float S1 = 0.38268343236508977173f;
    const float R2 = 0.70710678118654752440f;
    float2 t0[4], t1[4], t2[4], t3[4];
    r4core(x[0], x[4], x[8],  x[12], t0[0], t0[1], t0[2], t0[3]);
    r4core(x[1], x[5], x[9],  x[13], t1[0], t1[1], t1[2], t1[3]);
    r4core(x[2], x[6], x[10], x[14], t2[0], t2[1], t2[2], t2[3]);
    r4core(x[3], x[7], x[11], x[15], t3[0], t3[1], t3[2], t3[3]);
    t1[1] = cmul(t1[1], make_float2( C1, -S1));
    t1[2] = cmul(t1[2], make_float2( R2, -R2));
    t1[3] = cmul(t1[3], make_float2( S1, -C1));
    t2[1] = cmul(t2[1], make_float2( R2, -R2));
    t2[2] = make_float2(t2[2].y, -t2[2].x);
    t2[3] = cmul(t2[3], make_float2(-R2, -R2));
    t3[1] = cmul(t3[1], make_float2( S1, -C1));
    t3[2] = cmul(t3[2], make_float2(-R2, -R2));
    t3[3] = cmul(t3[3], make_float2(-C1,  S1));
    r4core(t0[0], t1[0], t2[0], t3[0], X[0], X[4], X[8],  X[12]);
    r4core(t0[1], t1[1], t2[1], t3[1], X[1], X[5], X[9],  X[13]);
    r4core(t0[2], t1[2], t2[2], t3[2], X[2], X[6], X[10], X[14]);
    r4core(t0[3], t1[3], t2[3], t3[3], X[3], X[7], X[11], X[15]);
}

__device__ __forceinline__ void dft8(const float2* x, float2* X) {
    const float R2 = 0.70710678118654752440f;
    float2 E0, E1, E2, E3, O0, O1, O2, O3;
    r4core(x[0], x[2], x[4], x[6], E0, E1, E2, E3);
    r4core(x[1], x[3], x[5], x[7], O0, O1, O2, O3);
    float2 T1 = cmul(O1, make_float2( R2, -R2));
    float2 T2 = make_float2(O2.y, -O2.x);
    float2 T3 = cmul(O3, make_float2(-R2, -R2));
    X[0] = make_float2(E0.x + O0.x, E0.y + O0.y);
    X[4] = make_float2(E0.x - O0.x, E0.y - O0.y);
    X[1] = make_float2(E1.x + T1.x, E1.y + T1.y);
    X[5] = make_float2(E1.x - T1.x, E1.y - T1.y);
    X[2] = make_float2(E2.x + T2.x, E2.y + T2.y);
    X[6] = make_float2(E2.x - T2.x, E2.y - T2.y);
    X[3] = make_float2(E3.x + T3.x, E3.y + T3.y);
    X[7] = make_float2(E3.x - T3.x, E3.y - T3.y);
}

// Y[k] = A[k]*H[k] from packed-pair spectrum values zk=Z[k], zn=Z[N-k]
__device__ __forceinline__ float2 unpackY(float2 zk, float2 zn) {
    float2 A  = make_float2(0.5f * (zk.x + zn.x), 0.5f * (zk.y - zn.y));
    float2 Dv = make_float2(zk.x - zn.x, zk.y + zn.y);
    float2 H  = make_float2(0.5f * Dv.y, -0.5f * Dv.x);
    return cmul(A, H);
}

// Given Ym = Y[m], Yc = Y[NH-m], angle th = 2*pi*m/NFFT:
//   E = (Ym + conj Yc)/2, O = e^{+i th} * (Ym - conj Yc)/2
//   Wv[m]    = conj(V[m])    = (E.x - O.y, -E.y - O.x)
//   Wv[NH-m] = conj(V[NH-m]) = (E.x + O.y,  E.y - O.x)
__device__ __forceinline__ void c2rsplit(float2 Ym, float2 Yc, float th,
                                         float2& wm, float2& wmir) {
    float2 E = make_float2(0.5f * (Ym.x + Yc.x), 0.5f * (Ym.y - Yc.y));
    float2 G = make_float2(0.5f * (Ym.x - Yc.x), 0.5f * (Ym.y + Yc.y));
    float sn, cs; __sincosf(th, &sn, &cs);
    float2 O = cmul(make_float2(cs, sn), G);
    wm   = make_float2(E.x - O.y, -E.y - O.x);
    wmir = make_float2(E.x + O.y,  E.y - O.x);
}

// ---------------- pack: z = audio + i*flip(ir), transposed G0[n1*N2 + n2]
__global__ void pack_kernel(const float* __restrict__ audio, int N,
                            const float* __restrict__ ir, int M,
                            float2* __restrict__ G0) {
    __shared__ float2 tile[32][33];
    if (blockIdx.x == 0 && blockIdx.y == 0 && threadIdx.x == 0 && threadIdx.y == 0)
        g_max_bits = 0u;
    int n2_0 = blockIdx.x * 32;
    int n1_0 = blockIdx.y * 32;
    int tx = threadIdx.x;
    #pragma unroll
    for (int r = 0; r < 4; r++) {
        int ty = threadIdx.y + (r << 3);
        int i = (n1_0 + tx) + N1 * (n2_0 + ty);
        float re = (i < N) ? audio[i] : 0.0f;
        float im = (i < M) ? ir[M - 1 - i] : 0.0f;
        tile[ty][tx] = make_float2(re, im);
    }
    __syncthreads();
    #pragma unroll
    for (int r = 0; r < 4; r++) {
        int ty = threadIdx.y + (r << 3);
        G0[(size_t)(n1_0 + ty) * N2 + n2_0 + tx] = tile[tx][ty];
    }
}

// ---------------- forward rows: 4096-pt FFT per n1, 256 threads
__global__ void fft_rows16(const float2* __restrict__ in, float2* __restrict__ out) {
    extern __shared__ float2 sm[];
    float2* bA = sm;
    float2* bB = sm + SMPAD_R;
    int n1 = blockIdx.x;
    int t = threadIdx.x;
    const float2* row = in + (size_t)n1 * N2;
    float2* orow = out + (size_t)n1 * N2;
    float2 x[16], X[16];

    #pragma unroll
    for (int u = 0; u < 16; u++) x[u] = row[t + (u << 8)];
    dft16(x, X);
    {
        float2 w1 = twid((6.2831853071795865f / 4096.0f) * (float)t);
        float2 cur = make_float2(1.0f, 0.0f);
        #pragma unroll
        for (int r = 0; r < 16; r++) { bA[SW(16 * t + r)] = cmul(X[r], cur); cur = cmul(cur, w1); }
    }
    __syncthreads();

    #pragma unroll
    for (int u = 0; u < 16; u++) x[u] = bA[SW(t + (u << 8))];
    dft16(x, X);
    {
        int q = t & 15, p = t >> 4;
        float2 w1 = twid((6.2831853071795865f / 256.0f) * (float)p);
        float2 cur = make_float2(1.0f, 0.0f);
        int base = q + (p << 8);
        #pragma unroll
        for (int r = 0; r < 16; r++) { bB[SW(base + 16 * r)] = cmul(X[r], cur); cur = cmul(cur, w1); }
    }
    __syncthreads();

    #pragma unroll
    for (int u = 0; u < 16; u++) x[u] = bB[SW(t + (u << 8))];
    dft16(x, X);
    {
        const float c0 = 6.2831853071795865f / (float)NFFT;
        float2 cur = twid(c0 * (float)(n1 * t));      // n1*k2 < 2^24: exact
        float2 V   = twid(c0 * (float)(n1 << 8));
        #pragma unroll
        for (int r = 0; r < 16; r++) { orow[t + (r << 8)] = cmul(X[r], cur); cur = cmul(cur, V); }
    }
}

// ---------------- forward cols: 768-pt FFTs over TILE=8 cols, stride N2=4096
__global__ void fft_cols768f(const float2* __restrict__ in, float2* __restrict__ outc) {
    extern __shared__ float2 sm[];
    float2* bA = sm;
    float2* bB = sm + SMPAD_C;
    int k20 = blockIdx.x * TILE;
    int t = threadIdx.x;
    int b = t & (TILE - 1), tt = t >> LOG2TILE;    // tt in [0,48)
    float2 x[16], X[16];

    #pragma unroll
    for (int u = 0; u < 16; u++)
        x[u] = in[(size_t)(tt + 48 * u) * N2 + k20 + b];
    dft16(x, X);
    {
        float2 w1 = twid((6.2831853071795865f / 768.0f) * (float)tt);
        float2 cur = make_float2(1.0f, 0.0f);
        #pragma unroll
        for (int r = 0; r < 16; r++) {
            bA[SW(((16 * tt + r) << LOG2TILE) + b)] = cmul(X[r], cur); cur = cmul(cur, w1);
        }
    }
    __syncthreads();

    #pragma unroll
    for (int u = 0; u < 16; u++) x[u] = bA[SW(((tt + 48 * u) << LOG2TILE) + b)];
    dft16(x, X);
    {
        int q = tt & 15, p = tt >> 4;
        float2 w1 = twid((6.2831853071795865f / 48.0f) * (float)p);
        float2 cur = make_float2(1.0f, 0.0f);
        int base = q + (p << 8);
        #pragma unroll
        for (int r = 0; r < 16; r++) {
            bB[SW(((base + 16 * r) << LOG2TILE) + b)] = cmul(X[r], cur); cur = cmul(cur, w1);
        }
    }
    __syncthreads();

    const float SQ32 = 0.86602540378443864676f;
    for (int q = tt; q < 256; q += 48) {
        float2 a  = bB[SW(((q      ) << LOG2TILE) + b)];
        float2 bb = bB[SW(((q + 256) << LOG2TILE) + b)];
        float2 c  = bB[SW(((q + 512) << LOG2TILE) + b)];
        float2 ts = make_float2(bb.x + c.x, bb.y + c.y);
        float2 u  = make_float2(bb.x - c.x, bb.y - c.y);
        float2 e0 = make_float2(a.x + ts.x, a.y + ts.y);
        float rx = a.x - 0.5f * ts.x, ry = a.y - 0.5f * ts.y;
        float2 e1 = make_float2(rx + SQ32 * u.y, ry - SQ32 * u.x);
        float2 e2 = make_float2(rx - SQ32 * u.y, ry + SQ32 * u.x);
        int kc = k20 + b;
        outc[kc + ((q      ) << 12)] = e0;
        outc[kc + ((q + 256) << 12)] = e1;
        outc[kc + ((q + 512) << 12)] = e2;
    }
}

// ---------------- specmul + C2R split. m = n1 + 768*n2v (n2v < 2048).
// pairA: n1 in [1,384); mirror row 768-n1, mirror col 2047-n2v.
__global__ void specmul_pairA(const float2* __restrict__ Z, float2* __restrict__ W) {
    __shared__ float2 tC[32][33];
    __shared__ float2 tM[32][33];
    int n2_0 = blockIdx.x * 32;       // 64 tiles over [0,2048)
    int n1_0 = blockIdx.y * 32;       // 12 tiles over [0,384)
    int tx = threadIdx.x;
    int n1 = n1_0 + tx;
    const float c1 = 6.2831853071795865f / (float)NFFT;
    #pragma unroll
    for (int r = 0; r < 4; r++) {
        int ty = threadIdx.y + (r << 3);
        int n2 = n2_0 + ty;
        if (n1 != 0) {
            int m = n1 + 768 * n2;                 // in (0, NH)
            float2 Ym = unpackY(Z[m], Z[NFFT - m]);
            float2 Yc = unpackY(Z[NH - m], Z[NH + m]);
            float2 wm, wmir;
            c2rsplit(Ym, Yc, c1 * (float)m, wm, wmir);
            tC[ty][tx] = wm;
            tM[ty][tx] = wmir;
        }
    }
    __syncthreads();
    #pragma unroll
    for (int r = 0; r < 4; r++) {
        int ty = threadIdx.y + (r << 3);
        int row = n1_0 + ty;
        W[(size_t)row * N2V + n2_0 + tx] = tC[tx][ty];   // row 0 garbage -> pairB
        if (row > 0)
            W[(size_t)(768 - row) * N2V + (2047 - (n2_0 + tx))] = tM[tx][ty];
    }
}

// pairB: rows n1 = 0 (incl. m=0 special) and n1 = 384.
__global__ void specmul_pairB(const float2* __restrict__ Z, float2* __restrict__ W) {
    int tid = blockIdx.x * blockDim.x + threadIdx.x;
    const float c1 = 6.2831853071795865f / (float)NFFT;
    if (tid == 0) {
        float2 z0 = Z[0], zh = Z[NH];
        float Y0 = z0.x * z0.y;                // Y[0], real
        float Yh = zh.x * zh.y;                // Y[NH], real
        W[0] = make_float2(0.5f * (Y0 + Yh), -0.5f * (Y0 - Yh));
    } else if (tid <= 1024) {                  // n1=0: m = 768*n2, n2 in [1,1024]
        int n2 = tid;
        int m = 768 * n2;
        float2 Ym = unpackY(Z[m], Z[NFFT - m]);
        float2 Yc = unpackY(Z[NH - m], Z[NH + m]);
        float2 wm, wmir;
        c2rsplit(Ym, Yc, c1 * (float)m, wm, wmir);
        W[n2] = wm;
        W[2048 - n2] = wmir;
    } else if (tid <= 2048) {                  // n1=384: n2 in [0,1023]
        int n2 = tid - 1025;
        int m = 384 + 768 * n2;
        float2 Ym = unpackY(Z[m], Z[NFFT - m]);
        float2 Yc = unpackY(Z[NH - m], Z[NH + m]);
        float2 wm, wmir;
        c2rsplit(Ym, Yc, c1 * (float)m, wm, wmir);
        W[(size_t)384 * N2V + n2]          = wm;
        W[(size_t)384 * N2V + (2047 - n2)] = wmir;
    }
}

// ---------------- inverse rows: 2048-pt FFT per n1 (stages 16,16,8), 128 thr
__global__ void fft_rows2048(const float2* __restrict__ in, float2* __restrict__ out) {
    __shared__ float2 sm[2 * SMPAD_R2];          // 33,792 B
    float2* bA = sm;
    float2* bB = sm + SMPAD_R2;
    int n1 = blockIdx.x;
    int t = threadIdx.x;
    const float2* row = in + (size_t)n1 * N2V;
    float2* orow = out + (size_t)n1 * N2V;
    float2 x[16], X[16];

    // stage 1: radix-16, n=2048, s=1, m=128, p=t
    #pragma unroll
    for (int u = 0; u < 16; u++) x[u] = row[t + (u << 7)];
    dft16(x, X);
    {
        float2 w1 = twid((6.2831853071795865f / 2048.0f) * (float)t);
        float2 cur = make_float2(1.0f, 0.0f);
        #pragma unroll
        for (int r = 0; r < 16; r++) { bA[SW(16 * t + r)] = cmul(X[r], cur); cur = cmul(cur, w1); }
    }
    __syncthreads();

    // stage 2: radix-16, n=128, s=16, m=8; q=t&15, p=t>>4 (<8)
    #pragma unroll
    for (int u = 0; u < 16; u++) x[u] = bA[SW(t + (u << 7))];
    dft16(x, X);
    {
        int q = t & 15, p = t >> 4;
        float2 w1 = twid((6.2831853071795865f / 128.0f) * (float)p);
        float2 cur = make_float2(1.0f, 0.0f);
        int base = q + (p << 8);
        #pragma unroll
        for (int r = 0; r < 16; r++) { bB[SW(base + 16 * r)] = cmul(X[r], cur); cur = cmul(cur, w1); }
    }
    __syncthreads();

    // stage 3: radix-8, n=8, s=256, p=0; fused interdim twiddle + store
    {
        const float c0 = 6.2831853071795865f / (float)NH;
        float2 y[8], Y8[8];
        #pragma unroll
        for (int qq0 = 0; qq0 < 2; qq0++) {
            int q = t + (qq0 << 7);
            #pragma unroll
            for (int u = 0; u < 8; u++) y[u] = bB[SW(q + (u << 8))];
            dft8(y, Y8);
            float2 cur = twid(c0 * (float)(n1 * q));      // n1*k2 < 2^24: exact
            float2 V   = twid(c0 * (float)(n1 << 8));
            #pragma unroll
            for (int r = 0; r < 8; r++) { orow[q + (r << 8)] = cmul(Y8[r], cur); cur = cmul(cur, V); }
        }
    }
}

// ---------------- inverse cols: 768-pt over TILE=8 cols, stride N2V=2048.
// Epilogue: m = k2 + 2048*k1; v = (F.x, -F.y); y[2m]=v.x, y[2m+1]=v.y,
// stored as float2 at outv[m] when overlapping window; fused max-abs.
__global__ void fft_cols768v(const float2* __restrict__ in, float2* __restrict__ outv,
                             int lo, int hi) {
    extern __shared__ float2 sm[];
    float2* bA = sm;
    float2* bB = sm + SMPAD_C;
    int k20 = blockIdx.x * TILE;
    int t = threadIdx.x;
    int b = t & (TILE - 1), tt = t >> LOG2TILE;    // tt in [0,48)
    float2 x[16], X[16];

    #pragma unroll
    for (int u = 0; u < 16; u++)
        x[u] = in[(size_t)(tt + 48 * u) * N2V + k20 + b];
    dft16(x, X);
    {
        float2 w1 = twid((6.2831853071795865f / 768.0f) * (float)tt);
        float2 cur = make_float2(1.0f, 0.0f);
        #pragma unroll
        for (int r = 0; r < 16; r++) {
            bA[SW(((16 * tt + r) << LOG2TILE) + b)] = cmul(X[r], cur); cur = cmul(cur, w1);
        }
    }
    __syncthreads();

    #pragma unroll
    for (int u = 0; u < 16; u++) x[u] = bA[SW(((tt + 48 * u) << LOG2TILE) + b)];
    dft16(x, X);
    {
        int q = tt & 15, p = tt >> 4;
        float2 w1 = twid((6.2831853071795865f / 48.0f) * (float)p);
        float2 cur = make_float2(1.0f, 0.0f);
        int base = q + (p << 8);
        #pragma unroll
        for (int r = 0; r < 16; r++) {
            bB[SW(((base + 16 * r) << LOG2TILE) + b)] = cmul(X[r], cur); cur = cmul(cur, w1);
        }
    }
    __syncthreads();

    const float SQ32 = 0.86602540378443864676f;
    float lmax = 0.0f;
    unsigned wlen = (unsigned)(hi - lo);
    for (int q = tt; q < 256; q += 48) {
        float2 a  = bB[SW(((q      ) << LOG2TILE) + b)];
        float2 bb = bB[SW(((q + 256) << LOG2TILE) + b)];
        float2 c  = bB[SW(((q + 512) << LOG2TILE) + b)];
        float2 ts = make_float2(bb.x + c.x, bb.y + c.y);
        float2 u  = make_float2(bb.x - c.x, bb.y - c.y);
        float2 e0 = make_float2(a.x + ts.x, a.y + ts.y);
        float rx = a.x - 0.5f * ts.x, ry = a.y - 0.5f * ts.y;
        float2 e1 = make_float2(rx + SQ32 * u.y, ry - SQ32 * u.x);
        float2 e2 = make_float2(rx - SQ32 * u.y, ry + SQ32 * u.x);
        int kc = k20 + b;
        #pragma unroll
        for (int r = 0; r < 3; r++) {
            float2 e = (r == 0) ? e0 : (r == 1) ? e1 : e2;
            int m = kc + ((q + 256 * r) << 11);
            int j0 = 2 * m;
            float2 v = make_float2(e.x, -e.y);
            if (j0 + 1 >= lo && j0 < hi) outv[m] = v;
            if ((unsigned)(j0     - lo) < wlen) lmax = fmaxf(lmax, fabsf(v.x));
            if ((unsigned)(j0 + 1 - lo) < wlen) lmax = fmaxf(lmax, fabsf(v.y));
        }
    }
    #pragma unroll
    for (int off = 16; off > 0; off >>= 1)
        lmax = fmaxf(lmax, __shfl_xor_sync(0xffffffffu, lmax, off));
    __shared__ float wmax[12];
    int lane = t & 31, w = t >> 5;
    if (lane == 0) wmax[w] = lmax;
    __syncthreads();
    if (t == 0) {
        float mx = wmax[0];
        #pragma unroll
        for (int j = 1; j < 12; j++) mx = fmaxf(mx, wmax[j]);
        atomicMax(&g_max_bits, __float_as_uint(mx));   // values >= 0
    }
}

// ---------------- final: out[i] = y[M-1+i] / max
__global__ void final_kernel(const float* __restrict__ yf,
                             float* __restrict__ out, int N, int M) {
    int i = blockIdx.x * blockDim.x + threadIdx.x;
    if (i < N) {
        float mx = __uint_as_float(g_max_bits);
        out[i] = yf[(M - 1) + i] / mx;
    }
}

extern "C" void kernel_launch(void* const* d_in, const int* in_sizes, int n_in,
                              void* d_out, int out_size) {
    const float* audio = (const float*)d_in[0];
    const float* ir    = (const float*)d_in[1];
    const int N = in_sizes[0];
    const int M = in_sizes[1];
    float* out = (float*)d_out;

    float2 *A = nullptr, *B = nullptr;
    cudaGetSymbolAddress((void**)&A, g_bufA);
    cudaGetSymbolAddress((void**)&B, g_bufB);

    const int SMEM_R = 2 * SMPAD_R * (int)sizeof(float2);   // 67584
    const int SMEM_C = 2 * SMPAD_C * (int)sizeof(float2);   // 101376
    cudaFuncSetAttribute(fft_rows16, cudaFuncAttributeMaxDynamicSharedMemorySize, SMEM_R);
    cudaFuncSetAttribute(fft_cols768f, cudaFuncAttributeMaxDynamicSharedMemorySize, SMEM_C);
    cudaFuncSetAttribute(fft_cols768v, cudaFuncAttributeMaxDynamicSharedMemorySize, SMEM_C);

    dim3 tblk(32, 8);

    // forward: pack -> A, rows A->B, cols B->A  (Z natural order in A)
    pack_kernel<<<dim3(N2 / 32, N1 / 32), tblk>>>(audio, N, ir, M, A);
    fft_rows16<<<N1, 256, SMEM_R>>>(A, B);
    fft_cols768f<<<N2 / TILE, 384, SMEM_C>>>(B, A);

    // specmul + C2R split: A -> B  (Wv transposed [n1*2048 + n2])
    specmul_pairA<<<dim3(N2V / 32, 12), tblk>>>(A, B);
    specmul_pairB<<<9, 256>>>(A, B);

    // half-size inverse: rows B->A, cols A-> y pairs in B (+ fused max)
    fft_rows2048<<<N1, 128>>>(B, A);
    fft_cols768v<<<N2V / TILE, 384, SMEM_C>>>(A, B, M - 1, M - 1 + N);

    final_kernel<<<(N + 255) / 256, 256>>>((const float*)B, out, N, M);
}

// round 7
// speedup vs baseline: 3.9573x; 1.1380x over previous
#include <cuda_runtime.h>

// Reverb via four-step FFT convolution, cols-first orientation.
// NFFT = 3*2^20 = 768*4096 >= N + 2(M-1); NH = NFFT/2 = 768*2048.
// Forward (z = audio + i*flip(ir), packed on the fly):
//   n = n2' + 4096*n1', k = k1' + 768*k2'
//   stage A (fwd_cols768): 768-FFT over n1' (input stride 4096, direct from
//     audio/ir), epilogue twiddle e^{-2pi i n2' k1'/NFFT}; writes G[k1'][n2'].
//   stage B (fwd_rows4096): plain 4096-FFT per row; writes Zrow[k1'][k2'].
// specmul + C2R split (all row-coalesced in Zrow layout):
//   Y[m] = A[m]*H[m]; V[m] packs y[2m]+i*y[2m+1]; store conj(V) as W[m1][m2],
//   m = m1 + 768*m2.
// Inverse (forward-of-conj): rows2048 over m2 (+twiddle), cols768 over m1,
//   emits y pairs windowed with fused max-abs; final normalizes.

#define NFFT   3145728
#define NH     1572864
#define N2     4096
#define N2V    2048
#define TILE   8
#define LOG2TILE 3
#define SMPAD_R  4224         // SW(4095)=4222
#define SMPAD_R2 2112         // SW(2047)=2110
#define SMPAD_C  6336         // SW(6143)=6334

__device__ float2 g_bufA[1 << 22];
__device__ float2 g_bufB[1 << 22];
__device__ unsigned int g_max_bits;

__device__ __forceinline__ float2 cmul(float2 a, float2 b) {
    return make_float2(fmaf(a.x, b.x, -(a.y * b.y)),
                       fmaf(a.x, b.y,  (a.y * b.x)));
}
__device__ __forceinline__ float2 twid(float ang) {   // e^{-i ang}
    float sn, cs; __sincosf(ang, &sn, &cs);
    return make_float2(cs, -sn);
}
__device__ __forceinline__ int SW(int x) { return x + (x >> 5); }

__device__ __forceinline__ void r4core(float2 a, float2 b, float2 c, float2 d,
                                       float2& e0, float2& e1, float2& e2, float2& e3) {
    float2 apc = make_float2(a.x + c.x, a.y + c.y);
    float2 amc = make_float2(a.x - c.x, a.y - c.y);
    float2 bpd = make_float2(b.x + d.x, b.y + d.y);
    float2 bmd = make_float2(b.x - d.x, b.y - d.y);
    e0 = make_float2(apc.x + bpd.x, apc.y + bpd.y);
    e1 = make_float2(amc.x + bmd.y, amc.y - bmd.x);
    e2 = make_float2(apc.x - bpd.x, apc.y - bpd.y);
    e3 = make_float2(amc.x - bmd.y, amc.y + bmd.x);
}

__device__ __forceinline__ void dft16(const float2* x, float2* X) {
    const float C1 = 0.92387953251128675613f;
    const float S1 = 0.38268343236508977173f;
    const float R2 = 0.70710678118654752440f;
    float2 t0[4], t1[4], t2[4], t3[4];
    r4core(x[0], x[4], x[8],  x[12], t0[0], t0[1], t0[2], t0[3]);
    r4core(x[1], x[5], x[9],  x[13], t1[0], t1[1], t1[2], t1[3]);
    r4core(x[2], x[6], x[10], x[14], t2[0], t2[1], t2[2], t2[3]);
    r4core(x[3], x[7], x[11], x[15], t3[0], t3[1], t3[2], t3[3]);
    t1[1] = cmul(t1[1], make_float2( C1, -S1));
    t1[2] = cmul(t1[2], make_float2( R2, -R2));
    t1[3] = cmul(t1[3], make_float2( S1, -C1));
    t2[1] = cmul(t2[1], make_float2( R2, -R2));
    t2[2] = make_float2(t2[2].y, -t2[2].x);
    t2[3] = cmul(t2[3], make_float2(-R2, -R2));
    t3[1] = cmul(t3[1], make_float2( S1, -C1));
    t3[2] = cmul(t3[2], make_float2(-R2, -R2));
    t3[3] = cmul(t3[3], make_float2(-C1,  S1));
    r4core(t0[0], t1[0], t2[0], t3[0], X[0], X[4], X[8],  X[12]);
    r4core(t0[1], t1[1], t2[1], t3[1], X[1], X[5], X[9],  X[13]);
    r4core(t0[2], t1[2], t2[2], t3[2], X[2], X[6], X[10], X[14]);
    r4core(t0[3], t1[3], t2[3], t3[3], X[3], X[7], X[11], X[15]);
}

__device__ __forceinline__ void dft8(const float2* x, float2* X) {
    const float R2 = 0.70710678118654752440f;
    float2 E0, E1, E2, E3, O0, O1, O2, O3;
    r4core(x[0], x[2], x[4], x[6], E0, E1, E2, E3);
    r4core(x[1], x[3], x[5], x[7], O0, O1, O2, O3);
    float2 T1 = cmul(O1, make_float2( R2, -R2));
    float2 T2 = make_float2(O2.y, -O2.x);
    float2 T3 = cmul(O3, make_float2(-R2, -R2));
    X[0] = make_float2(E0.x + O0.x, E0.y + O0.y);
    X[4] = make_float2(E0.x - O0.x, E0.y - O0.y);
    X[1] = make_float2(E1.x + T1.x, E1.y + T1.y);
    X[5] = make_float2(E1.x - T1.x, E1.y - T1.y);
    X[2] = make_float2(E2.x + T2.x, E2.y + T2.y);
    X[6] = make_float2(E2.x - T2.x, E2.y - T2.y);
    X[3] = make_float2(E3.x + T3.x, E3.y + T3.y);
    X[7] = make_float2(E3.x - T3.x, E3.y - T3.y);
}

// Y[k] = A[k]*H[k] from packed-pair spectrum: zk = Z[k], zn = Z[NFFT-k]
__device__ __forceinline__ float2 unpackY(float2 zk, float2 zn) {
    float2 A  = make_float2(0.5f * (zk.x + zn.x), 0.5f * (zk.y - zn.y));
    float2 Dv = make_float2(zk.x - zn.x, zk.y + zn.y);
    float2 H  = make_float2(0.5f * Dv.y, -0.5f * Dv.x);
    return cmul(A, H);
}

// C2R split: Ym = Y[m], Yc = Y[NH-m], th = 2*pi*m/NFFT.
// wm = conj(V[m]), wmir = conj(V[NH-m]).
__device__ __forceinline__ void c2rsplit(float2 Ym, float2 Yc, float th,
                                         float2& wm, float2& wmir) {
    float2 E = make_float2(0.5f * (Ym.x + Yc.x), 0.5f * (Ym.y - Yc.y));
    float2 G = make_float2(0.5f * (Ym.x - Yc.x), 0.5f * (Ym.y + Yc.y));
    float sn, cs; __sincosf(th, &sn, &cs);
    float2 O = cmul(make_float2(cs, sn), G);
    wm   = make_float2(E.x - O.y, -E.y - O.x);
    wmir = make_float2(E.x + O.y,  E.y - O.x);
}

// ---------------- fwd_cols768: 768-pt FFT over n1' (stride 4096), TILE=8
// n2' columns, direct input packing, epilogue interdim twiddle -> G[k1'][n2']
__global__ void fwd_cols768(const float* __restrict__ audio, int N,
                            const float* __restrict__ ir, int M,
                            float2* __restrict__ G) {
    extern __shared__ float2 sm[];
    float2* bA = sm;
    float2* bB = sm + SMPAD_C;
    int k20 = blockIdx.x * TILE;
    int t = threadIdx.x;
    int b = t & (TILE - 1), tt = t >> LOG2TILE;    // tt in [0,48)
    if (blockIdx.x == 0 && t == 0) g_max_bits = 0u;
    float2 x[16], X[16];

    // stage 1: n=768, s=1, m=48, p=tt; input z[n2' + 4096*n1'] built on the fly
    #pragma unroll
    for (int u = 0; u < 16; u++) {
        int n = (tt + 48 * u) * 4096 + k20 + b;
        float re = (n < N) ? audio[n] : 0.0f;
        float im = (n < M) ? ir[M - 1 - n] : 0.0f;
        x[u] = make_float2(re, im);
    }
    dft16(x, X);
    {
        float2 w1 = twid((6.2831853071795865f / 768.0f) * (float)tt);
        float2 cur = make_float2(1.0f, 0.0f);
        #pragma unroll
        for (int r = 0; r < 16; r++) {
            bA[SW(((16 * tt + r) << LOG2TILE) + b)] = cmul(X[r], cur); cur = cmul(cur, w1);
        }
    }
    __syncthreads();

    // stage 2: n=48, s=16, m=3
    #pragma unroll
    for (int u = 0; u < 16; u++) x[u] = bA[SW(((tt + 48 * u) << LOG2TILE) + b)];
    dft16(x, X);
    {
        int q = tt & 15, p = tt >> 4;
        float2 w1 = twid((6.2831853071795865f / 48.0f) * (float)p);
        float2 cur = make_float2(1.0f, 0.0f);
        int base = q + (p << 8);
        #pragma unroll
        for (int r = 0; r < 16; r++) {
            bB[SW(((base + 16 * r) << LOG2TILE) + b)] = cmul(X[r], cur); cur = cmul(cur, w1);
        }
    }
    __syncthreads();

    // stage 3: radix-3 (p=0) + interdim twiddle e^{-2pi i n2'k1'/NFFT} + store
    const float SQ32 = 0.86602540378443864676f;
    const float c0 = 6.2831853071795865f / (float)NFFT;
    int kc = k20 + b;                              // n2'
    for (int q = tt; q < 256; q += 48) {
        float2 a  = bB[SW(((q      ) << LOG2TILE) + b)];
        float2 bb = bB[SW(((q + 256) << LOG2TILE) + b)];
        float2 c  = bB[SW(((q + 512) << LOG2TILE) + b)];
        float2 ts = make_float2(bb.x + c.x, bb.y + c.y);
        float2 u  = make_float2(bb.x - c.x, bb.y - c.y);
        float2 e0 = make_float2(a.x + ts.x, a.y + ts.y);
        float rx = a.x - 0.5f * ts.x, ry = a.y - 0.5f * ts.y;
        float2 e1 = make_float2(rx + SQ32 * u.y, ry - SQ32 * u.x);
        float2 e2 = make_float2(rx - SQ32 * u.y, ry + SQ32 * u.x);
        // k1' = q, q+256, q+512 ; n2'*k1' <= 4095*767 < 2^22: float-exact
        G[(size_t)(q      ) * N2 + kc] = cmul(e0, twid(c0 * (float)(kc * (q      ))));
        G[(size_t)(q + 256) * N2 + kc] = cmul(e1, twid(c0 * (float)(kc * (q + 256))));
        G[(size_t)(q + 512) * N2 + kc] = cmul(e2, twid(c0 * (float)(kc * (q + 512))));
    }
}

// ---------------- fwd_rows4096: plain 4096-pt FFT per row k1'
__global__ void fwd_rows4096(const float2* __restrict__ in, float2* __restrict__ out) {
    extern __shared__ float2 sm[];
    float2* bA = sm;
    float2* bB = sm + SMPAD_R;
    int t = threadIdx.x;
    const float2* row = in + (size_t)blockIdx.x * N2;
    float2* orow = out + (size_t)blockIdx.x * N2;
    float2 x[16], X[16];

    #pragma unroll
    for (int u = 0; u < 16; u++) x[u] = row[t + (u << 8)];
    dft16(x, X);
    {
        float2 w1 = twid((6.2831853071795865f / 4096.0f) * (float)t);
        float2 cur = make_float2(1.0f, 0.0f);
        #pragma unroll
        for (int r = 0; r < 16; r++) { bA[SW(16 * t + r)] = cmul(X[r], cur); cur = cmul(cur, w1); }
    }
    __syncthreads();

    #pragma unroll
    for (int u = 0; u < 16; u++) x[u] = bA[SW(t + (u << 8))];
    dft16(x, X);
    {
        int q = t & 15, p = t >> 4;
        float2 w1 = twid((6.2831853071795865f / 256.0f) * (float)p);
        float2 cur = make_float2(1.0f, 0.0f);
        int base = q + (p << 8);
        #pragma unroll
        for (int r = 0; r < 16; r++) { bB[SW(base + 16 * r)] = cmul(X[r], cur); cur = cmul(cur, w1); }
    }
    __syncthreads();

    #pragma unroll
    for (int u = 0; u < 16; u++) x[u] = bB[SW(t + (u << 8))];
    dft16(x, X);
    #pragma unroll
    for (int r = 0; r < 16; r++) orow[t + (r << 8)] = X[r];
}

// ---------------- specmul + C2R, all row-coalesced. Zrow[k1'][k2'] holds
// Z[k1' + 768*k2']. m = r + 768*c, c in [0,2048):
//   Z[m]=[r][c], Z[NFFT-m]=[768-r][4095-c], Z[NH-m]=[768-r][2047-c],
//   Z[NH+m]=[r][2048+c].  W[m1][m2]: wm->[r][c], wmir->[768-r][2047-c].
__global__ void specmul_rows(const float2* __restrict__ Zr, float2* __restrict__ W) {
    int c = blockIdx.x * blockDim.x + threadIdx.x;   // [0,2048)
    int r = blockIdx.y + 1;                          // [1,384)
    const float c1 = 6.2831853071795865f / (float)NFFT;
    float2 zk  = Zr[(size_t)r * N2 + c];
    float2 znf = Zr[(size_t)(768 - r) * N2 + 4095 - c];
    float2 zh1 = Zr[(size_t)(768 - r) * N2 + 2047 - c];
    float2 zh2 = Zr[(size_t)r * N2 + 2048 + c];
    float2 Ym = unpackY(zk, znf);
    float2 Yc = unpackY(zh1, zh2);
    int m = r + 768 * c;                             // < NH < 2^24: float-exact
    float2 wm, wmir;
    c2rsplit(Ym, Yc, c1 * (float)m, wm, wmir);
    W[(size_t)r * N2V + c] = wm;
    W[(size_t)(768 - r) * N2V + 2047 - c] = wmir;
}

// edge rows r = 0 and r = 384 (self-mirror rows) + m = 0
__global__ void specmul_edge(const float2* __restrict__ Zr, float2* __restrict__ W) {
    int tid = blockIdx.x * blockDim.x + threadIdx.x;
    const float c1 = 6.2831853071795865f / (float)NFFT;
    if (tid == 0) {
        float2 z0 = Zr[0], zh = Zr[2048];            // Z[0], Z[NH]
        float Y0 = z0.x * z0.y;
        float Yh = zh.x * zh.y;
        W[0] = make_float2(0.5f * (Y0 + Yh), -0.5f * (Y0 - Yh));
    } else if (tid <= 1024) {                        // r=0: m = 768c, c in [1,1024]
        int c = tid;
        float2 zk  = Zr[c];
        float2 znf = Zr[4096 - c];
        float2 zh1 = Zr[2048 - c];
        float2 zh2 = Zr[2048 + c];
        float2 Ym = unpackY(zk, znf);
        float2 Yc = unpackY(zh1, zh2);
        float2 wm, wmir;
        c2rsplit(Ym, Yc, c1 * (float)(768 * c), wm, wmir);
        W[c] = wm;
        W[2048 - c] = wmir;
    } else if (tid <= 2048) {                        // r=384: c in [0,1023]
        int c = tid - 1025;
        size_t base = (size_t)384 * N2;
        float2 zk  = Zr[base + c];
        float2 znf = Zr[base + 4095 - c];
        float2 zh1 = Zr[base + 2047 - c];
        float2 zh2 = Zr[base + 2048 + c];
        float2 Ym = unpackY(zk, znf);
        float2 Yc = unpackY(zh1, zh2);
        float2 wm, wmir;
        c2rsplit(Ym, Yc, c1 * (float)(384 + 768 * c), wm, wmir);
        W[(size_t)384 * N2V + c]        = wm;
        W[(size_t)384 * N2V + 2047 - c] = wmir;
    }
}

// ---------------- inverse rows: 2048-pt FFT per m1 (16,16,8), 128 threads,
// epilogue interdim twiddle e^{-2pi i m1 j2/NH}
__global__ void fft_rows2048(const float2* __restrict__ in, float2* __restrict__ out) {
    __shared__ float2 sm[2 * SMPAD_R2];
    float2* bA = sm;
    float2* bB = sm + SMPAD_R2;
    int n1 = blockIdx.x;
    int t = threadIdx.x;
    const float2* row = in + (size_t)n1 * N2V;
    float2* orow = out + (size_t)n1 * N2V;
    float2 x[16], X[16];

    #pragma unroll
    for (int u = 0; u < 16; u++) x[u] = row[t + (u << 7)];
    dft16(x, X);
    {
        float2 w1 = twid((6.2831853071795865f / 2048.0f) * (float)t);
        float2 cur = make_float2(1.0f, 0.0f);
        #pragma unroll
        for (int r = 0; r < 16; r++) { bA[SW(16 * t + r)] = cmul(X[r], cur); cur = cmul(cur, w1); }
    }
    __syncthreads();

    #pragma unroll
    for (int u = 0; u < 16; u++) x[u] = bA[SW(t + (u << 7))];
    dft16(x, X);
    {
        int q = t & 15, p = t >> 4;
        float2 w1 = twid((6.2831853071795865f / 128.0f) * (float)p);
        float2 cur = make_float2(1.0f, 0.0f);
        int base = q + (p << 8);
        #pragma unroll
        for (int r = 0; r < 16; r++) { bB[SW(base + 16 * r)] = cmul(X[r], cur); cur = cmul(cur, w1); }
    }
    __syncthreads();

    {
        const float c0 = 6.2831853071795865f / (float)NH;
        float2 y[8], Y8[8];
        #pragma unroll
        for (int qq0 = 0; qq0 < 2; qq0++) {
            int q = t + (qq0 << 7);
            #pragma unroll
            for (int u = 0; u < 8; u++) y[u] = bB[SW(q + (u << 8))];
            dft8(y, Y8);
            float2 cur = twid(c0 * (float)(n1 * q));     // n1*q < 2^22: exact
            float2 V   = twid(c0 * (float)(n1 << 8));
            #pragma unroll
            for (int r = 0; r < 8; r++) { orow[q + (r << 8)] = cmul(Y8[r], cur); cur = cmul(cur, V); }
        }
    }
}

// ---------------- inverse cols: 768-pt over TILE=8 cols, stride N2V.
// Epilogue: t_idx = j2 + 2048*j1; v = (Re,-Im) -> y[2t],y[2t+1] as float2,
// windowed; fused max-abs.
__global__ void fft_cols768v(const float2* __restrict__ in, float2* __restrict__ outv,
                             int lo, int hi) {
    extern __shared__ float2 sm[];
    float2* bA = sm;
    float2* bB = sm + SMPAD_C;
    int k20 = blockIdx.x * TILE;
    int t = threadIdx.x;
    int b = t & (TILE - 1), tt = t >> LOG2TILE;
    float2 x[16], X[16];

    #pragma unroll
    for (int u = 0; u < 16; u++)
        x[u] = in[(size_t)(tt + 48 * u) * N2V + k20 + b];
    dft16(x, X);
    {
        float2 w1 = twid((6.2831853071795865f / 768.0f) * (float)tt);
        float2 cur = make_float2(1.0f, 0.0f);
        #pragma unroll
        for (int r = 0; r < 16; r++) {
            bA[SW(((16 * tt + r) << LOG2TILE) + b)] = cmul(X[r], cur); cur = cmul(cur, w1);
        }
    }
    __syncthreads();

    #pragma unroll
    for (int u = 0; u < 16; u++) x[u] = bA[SW(((tt + 48 * u) << LOG2TILE) + b)];
    dft16(x, X);
    {
        int q = tt & 15, p = tt >> 4;
        float2 w1 = twid((6.2831853071795865f / 48.0f) * (float)p);
        float2 cur = make_float2(1.0f, 0.0f);
        int base = q + (p << 8);
        #pragma unroll
        for (int r = 0; r < 16; r++) {
            bB[SW(((base + 16 * r) << LOG2TILE) + b)] = cmul(X[r], cur); cur = cmul(cur, w1);
        }
    }
    __syncthreads();

    const float SQ32 = 0.86602540378443864676f;
    float lmax = 0.0f;
    unsigned wlen = (unsigned)(hi - lo);
    for (int q = tt; q < 256; q += 48) {
        float2 a  = bB[SW(((q      ) << LOG2TILE) + b)];
        float2 bb = bB[SW(((q + 256) << LOG2TILE) + b)];
        float2 c  = bB[SW(((q + 512) << LOG2TILE) + b)];
        float2 ts = make_float2(bb.x + c.x, bb.y + c.y);
        float2 u  = make_float2(bb.x - c.x, bb.y - c.y);
        float2 e0 = make_float2(a.x + ts.x, a.y + ts.y);
        float rx = a.x - 0.5f * ts.x, ry = a.y - 0.5f * ts.y;
        float2 e1 = make_float2(rx + SQ32 * u.y, ry - SQ32 * u.x);
        float2 e2 = make_float2(rx - SQ32 * u.y, ry + SQ32 * u.x);
        int kc = k20 + b;
        #pragma unroll
        for (int r = 0; r < 3; r++) {
            float2 e = (r == 0) ? e0 : (r == 1) ? e1 : e2;
            int m = kc + ((q + 256 * r) << 11);
            int j0 = 2 * m;
            float2 v = make_float2(e.x, -e.y);
            if (j0 + 1 >= lo && j0 < hi) outv[m] = v;
            if ((unsigned)(j0     - lo) < wlen) lmax = fmaxf(lmax, fabsf(v.x));
            if ((unsigned)(j0 + 1 - lo) < wlen) lmax = fmaxf(lmax, fabsf(v.y));
        }
    }
    #pragma unroll
    for (int off = 16; off > 0; off >>= 1)
        lmax = fmaxf(lmax, __shfl_xor_sync(0xffffffffu, lmax, off));
    __shared__ float wmax[12];
    int lane = t & 31, w = t >> 5;
    if (lane == 0) wmax[w] = lmax;
    __syncthreads();
    if (t == 0) {
        float mx = wmax[0];
        #pragma unroll
        for (int j = 1; j < 12; j++) mx = fmaxf(mx, wmax[j]);
        atomicMax(&g_max_bits, __float_as_uint(mx));   // values >= 0
    }
}

// ---------------- final: out[i] = y[M-1+i] / max
__global__ void final_kernel(const float* __restrict__ yf,
                             float* __restrict__ out, int N, int M) {
    int i = blockIdx.x * blockDim.x + threadIdx.x;
    if (i < N) {
        float mx = __uint_as_float(g_max_bits);
        out[i] = yf[(M - 1) + i] / mx;
    }
}

extern "C" void kernel_launch(void* const* d_in, const int* in_sizes, int n_in,
                              void* d_out, int out_size) {
    const float* audio = (const float*)d_in[0];
    const float* ir    = (const float*)d_in[1];
    const int N = in_sizes[0];
    const int M = in_sizes[1];
    float* out = (float*)d_out;

    float2 *A = nullptr, *B = nullptr;
    cudaGetSymbolAddress((void**)&A, g_bufA);
    cudaGetSymbolAddress((void**)&B, g_bufB);

    const int SMEM_R = 2 * SMPAD_R * (int)sizeof(float2);   // 67584
    const int SMEM_C = 2 * SMPAD_C * (int)sizeof(float2);   // 101376
    cudaFuncSetAttribute(fwd_cols768,  cudaFuncAttributeMaxDynamicSharedMemorySize, SMEM_C);
    cudaFuncSetAttribute(fwd_rows4096, cudaFuncAttributeMaxDynamicSharedMemorySize, SMEM_R);
    cudaFuncSetAttribute(fft_cols768v, cudaFuncAttributeMaxDynamicSharedMemorySize, SMEM_C);

    // forward: cols (direct input, pack fused) -> A (G), rows A -> B (Zrow)
    fwd_cols768<<<N2 / TILE, 384, SMEM_C>>>(audio, N, ir, M, A);
    fwd_rows4096<<<768, 256, SMEM_R>>>(A, B);

    // specmul + C2R: B -> A  (W[m1][m2], row layout, all coalesced)
    specmul_rows<<<dim3(N2V / 256, 383), 256>>>(B, A);
    specmul_edge<<<9, 256>>>(B, A);

    // inverse: rows A -> B (H), cols B -> A (y pairs + fused max)
    fft_rows2048<<<768, 128>>>(A, B);
    fft_cols768v<<<N2V / TILE, 384, SMEM_C>>>(B, A, M - 1, M - 1 + N);

    final_kernel<<<(N + 255) / 256, 256>>>((const float*)A, out, N, M);
}

// round 8
// speedup vs baseline: 4.0831x; 1.0318x over previous
#include <cuda_runtime.h>

// Reverb via four-step FFT convolution, cols-first orientation, fused
// specmul + half-size inverse row FFT.
// NFFT = 3*2^20 = 768*4096 >= N + 2(M-1); NH = NFFT/2 = 768*2048.
//
// Forward (z = audio + i*flip(ir), packed on the fly):
//   fwd_cols768: 768-FFT over n1' (stride 4096, direct from inputs),
//     epilogue twiddle; writes G[k1'][n2'].
//   fwd_rows4096: 4096-FFT per row; writes Zrow[k1'][k2'] (Z[k1'+768k2']).
// spec_invrows (FUSED): per block, rows r and 768-r of Z -> unpack Y pairs,
//   C2R split -> W rows r, 768-r in smem -> two 2048-pt FFTs (+interdim
//   twiddle) -> H rows. Block 0 handles self-mirror rows 0 and 384.
// fft_cols768v: 768-FFT over m1, emits y pairs windowed + fused max-abs.
// final: normalize.

#define NFFT   3145728
#define NH     1572864
#define N2     4096
#define N2V    2048
#define TILE   8
#define LOG2TILE 3
#define SMPAD_R  4224         // SW(4095)=4222
#define SMPAD_R2 2112         // SW(2047)=2110
#define SMPAD_C  6336         // SW(6143)=6334

__device__ float2 g_bufA[1 << 22];
__device__ float2 g_bufB[1 << 22];
__device__ unsigned int g_max_bits;

__device__ __forceinline__ float2 cmul(float2 a, float2 b) {
    return make_float2(fmaf(a.x, b.x, -(a.y * b.y)),
                       fmaf(a.x, b.y,  (a.y * b.x)));
}
__device__ __forceinline__ float2 twid(float ang) {   // e^{-i ang}
    float sn, cs; __sincosf(ang, &sn, &cs);
    return make_float2(cs, -sn);
}
__device__ __forceinline__ int SW(int x) { return x + (x >> 5); }

__device__ __forceinline__ void r4core(float2 a, float2 b, float2 c, float2 d,
                                       float2& e0, float2& e1, float2& e2, float2& e3) {
    float2 apc = make_float2(a.x + c.x, a.y + c.y);
    float2 amc = make_float2(a.x - c.x, a.y - c.y);
    float2 bpd = make_float2(b.x + d.x, b.y + d.y);
    float2 bmd = make_float2(b.x - d.x, b.y - d.y);
    e0 = make_float2(apc.x + bpd.x, apc.y + bpd.y);
    e1 = make_float2(amc.x + bmd.y, amc.y - bmd.x);
    e2 = make_float2(apc.x - bpd.x, apc.y - bpd.y);
    e3 = make_float2(amc.x - bmd.y, amc.y + bmd.x);
}

__device__ __forceinline__ void dft16(const float2* x, float2* X) {
    const float C1 = 0.92387953251128675613f;
    const float S1 = 0.38268343236508977173f;
    const float R2 = 0.70710678118654752440f;
    float2 t0[4], t1[4], t2[4], t3[4];
    r4core(x[0], x[4], x[8],  x[12], t0[0], t0[1], t0[2], t0[3]);
    r4core(x[1], x[5], x[9],  x[13], t1[0], t1[1], t1[2], t1[3]);
    r4core(x[2], x[6], x[10], x[14], t2[0], t2[1], t2[2], t2[3]);
    r4core(x[3], x[7], x[11], x[15], t3[0], t3[1], t3[2], t3[3]);
    t1[1] = cmul(t1[1], make_float2( C1, -S1));
    t1[2] = cmul(t1[2], make_float2( R2, -R2));
    t1[3] = cmul(t1[3], make_float2( S1, -C1));
    t2[1] = cmul(t2[1], make_float2( R2, -R2));
    t2[2] = make_float2(t2[2].y, -t2[2].x);
    t2[3] = cmul(t2[3], make_float2(-R2, -R2));
    t3[1] = cmul(t3[1], make_float2( S1, -C1));
    t3[2] = cmul(t3[2], make_float2(-R2, -R2));
    t3[3] = cmul(t3[3], make_float2(-C1,  S1));
    r4core(t0[0], t1[0], t2[0], t3[0], X[0], X[4], X[8],  X[12]);
    r4core(t0[1], t1[1], t2[1], t3[1], X[1], X[5], X[9],  X[13]);
    r4core(t0[2], t1[2], t2[2], t3[2], X[2], X[6], X[10], X[14]);
    r4core(t0[3], t1[3], t2[3], t3[3], X[3], X[7], X[11], X[15]);
}

__device__ __forceinline__ void dft8(const float2* x, float2* X) {
    const float R2 = 0.70710678118654752440f;
    float2 E0, E1, E2, E3, O0, O1, O2, O3;
    r4core(x[0], x[2], x[4], x[6], E0, E1, E2, E3);
    r4core(x[1], x[3], x[5], x[7], O0, O1, O2, O3);
    float2 T1 = cmul(O1, make_float2( R2, -R2));
    float2 T2 = make_float2(O2.y, -O2.x);
    float2 T3 = cmul(O3, make_float2(-R2, -R2));
    X[0] = make_float2(E0.x + O0.x, E0.y + O0.y);
    X[4] = make_float2(E0.x - O0.x, E0.y - O0.y);
    X[1] = make_float2(E1.x + T1.x, E1.y + T1.y);
    X[5] = make_float2(E1.x - T1.x, E1.y - T1.y);
    X[2] = make_float2(E2.x + T2.x, E2.y + T2.y);
    X[6] = make_float2(E2.x - T2.x, E2.y - T2.y);
    X[3] = make_float2(E3.x + T3.x, E3.y + T3.y);
    X[7] = make_float2(E3.x - T3.x, E3.y - T3.y);
}

__device__ __forceinline__ float2 unpackY(float2 zk, float2 zn) {
    float2 A  = make_float2(0.5f * (zk.x + zn.x), 0.5f * (zk.y - zn.y));
    float2 Dv = make_float2(zk.x - zn.x, zk.y + zn.y);
    float2 H  = make_float2(0.5f * Dv.y, -0.5f * Dv.x);
    return cmul(A, H);
}

// C2R split: Ym=Y[m], Yc=Y[NH-m], th=2*pi*m/NFFT. wm=conj(V[m]), wmir=conj(V[NH-m]).
__device__ __forceinline__ void c2rsplit(float2 Ym, float2 Yc, float th,
                                         float2& wm, float2& wmir) {
    float2 E = make_float2(0.5f * (Ym.x + Yc.x), 0.5f * (Ym.y - Yc.y));
    float2 G = make_float2(0.5f * (Ym.x - Yc.x), 0.5f * (Ym.y + Yc.y));
    float sn, cs; __sincosf(th, &sn, &cs);
    float2 O = cmul(make_float2(cs, sn), G);
    wm   = make_float2(E.x - O.y, -E.y - O.x);
    wmir = make_float2(E.x + O.y,  E.y - O.x);
}

// ---------------- fwd_cols768: 768-pt FFT over n1' (stride 4096), TILE=8
__global__ void fwd_cols768(const float* __restrict__ audio, int N,
                            const float* __restrict__ ir, int M,
                            float2* __restrict__ G) {
    extern __shared__ float2 sm[];
    float2* bA = sm;
    float2* bB = sm + SMPAD_C;
    int k20 = blockIdx.x * TILE;
    int t = threadIdx.x;
    int b = t & (TILE - 1), tt = t >> LOG2TILE;
    if (blockIdx.x == 0 && t == 0) g_max_bits = 0u;
    float2 x[16], X[16];

    #pragma unroll
    for (int u = 0; u < 16; u++) {
        int n = (tt + 48 * u) * 4096 + k20 + b;
        float re = (n < N) ? audio[n] : 0.0f;
        float im = (n < M) ? ir[M - 1 - n] : 0.0f;
        x[u] = make_float2(re, im);
    }
    dft16(x, X);
    {
        float2 w1 = twid((6.2831853071795865f / 768.0f) * (float)tt);
        float2 cur = make_float2(1.0f, 0.0f);
        #pragma unroll
        for (int r = 0; r < 16; r++) {
            bA[SW(((16 * tt + r) << LOG2TILE) + b)] = cmul(X[r], cur); cur = cmul(cur, w1);
        }
    }
    __syncthreads();

    #pragma unroll
    for (int u = 0; u < 16; u++) x[u] = bA[SW(((tt + 48 * u) << LOG2TILE) + b)];
    dft16(x, X);
    {
        int q = tt & 15, p = tt >> 4;
        float2 w1 = twid((6.2831853071795865f / 48.0f) * (float)p);
        float2 cur = make_float2(1.0f, 0.0f);
        int base = q + (p << 8);
        #pragma unroll
        for (int r = 0; r < 16; r++) {
            bB[SW(((base + 16 * r) << LOG2TILE) + b)] = cmul(X[r], cur); cur = cmul(cur, w1);
        }
    }
    __syncthreads();

    const float SQ32 = 0.86602540378443864676f;
    const float c0 = 6.2831853071795865f / (float)NFFT;
    int kc = k20 + b;
    for (int q = tt; q < 256; q += 48) {
        float2 a  = bB[SW(((q      ) << LOG2TILE) + b)];
        float2 bb = bB[SW(((q + 256) << LOG2TILE) + b)];
        float2 c  = bB[SW(((q + 512) << LOG2TILE) + b)];
        float2 ts = make_float2(bb.x + c.x, bb.y + c.y);
        float2 u  = make_float2(bb.x - c.x, bb.y - c.y);
        float2 e0 = make_float2(a.x + ts.x, a.y + ts.y);
        float rx = a.x - 0.5f * ts.x, ry = a.y - 0.5f * ts.y;
        float2 e1 = make_float2(rx + SQ32 * u.y, ry - SQ32 * u.x);
        float2 e2 = make_float2(rx - SQ32 * u.y, ry + SQ32 * u.x);
        G[(size_t)(q      ) * N2 + kc] = cmul(e0, twid(c0 * (float)(kc * (q      ))));
        G[(size_t)(q + 256) * N2 + kc] = cmul(e1, twid(c0 * (float)(kc * (q + 256))));
        G[(size_t)(q + 512) * N2 + kc] = cmul(e2, twid(c0 * (float)(kc * (q + 512))));
    }
}

// ---------------- fwd_rows4096: plain 4096-pt FFT per row k1'
__global__ void fwd_rows4096(const float2* __restrict__ in, float2* __restrict__ out) {
    extern __shared__ float2 sm[];
    float2* bA = sm;
    float2* bB = sm + SMPAD_R;
    int t = threadIdx.x;
    const float2* row = in + (size_t)blockIdx.x * N2;
    float2* orow = out + (size_t)blockIdx.x * N2;
    float2 x[16], X[16];

    #pragma unroll
    for (int u = 0; u < 16; u++) x[u] = row[t + (u << 8)];
    dft16(x, X);
    {
        float2 w1 = twid((6.2831853071795865f / 4096.0f) * (float)t);
        float2 cur = make_float2(1.0f, 0.0f);
        #pragma unroll
        for (int r = 0; r < 16; r++) { bA[SW(16 * t + r)] = cmul(X[r], cur); cur = cmul(cur, w1); }
    }
    __syncthreads();

    #pragma unroll
    for (int u = 0; u < 16; u++) x[u] = bA[SW(t + (u << 8))];
    dft16(x, X);
    {
        int q = t & 15, p = t >> 4;
        float2 w1 = twid((6.2831853071795865f / 256.0f) * (float)p);
        float2 cur = make_float2(1.0f, 0.0f);
        int base = q + (p << 8);
        #pragma unroll
        for (int r = 0; r < 16; r++) { bB[SW(base + 16 * r)] = cmul(X[r], cur); cur = cmul(cur, w1); }
    }
    __syncthreads();

    #pragma unroll
    for (int u = 0; u < 16; u++) x[u] = bB[SW(t + (u << 8))];
    dft16(x, X);
    #pragma unroll
    for (int r = 0; r < 16; r++) orow[t + (r << 8)] = X[r];
}

// ---------------- spec_invrows (FUSED): 256 threads, 384 blocks.
// Block 0: W rows 0 and 384 (self-mirror). Block r (1..383): W rows r, 768-r.
// Phase 1 (all 256 threads): compute W rows into smem win[0], win[1].
// Phase 2 (two 128-thread groups): 2048-pt FFT per row + interdim twiddle.
__global__ void spec_invrows(const float2* __restrict__ Zr, float2* __restrict__ H) {
    extern __shared__ float2 sm[];
    float2* win[2] = { sm,               sm +     SMPAD_R2 };
    float2* bA [2] = { sm + 2*SMPAD_R2,  sm + 3 * SMPAD_R2 };
    int t = threadIdx.x;
    int r = blockIdx.x;
    const float c1 = 6.2831853071795865f / (float)NFFT;

    int row0, row1;
    if (r == 0) {
        row0 = 0; row1 = 384;
        // row 0: c in [1,1024]: zk=[0][c], znf=[0][4096-c], zh1=[0][2048-c], zh2=[0][2048+c]
        #pragma unroll
        for (int j = 0; j < 4; j++) {
            int c = 1 + t + (j << 8);          // [1,1024]
            float2 Ym = unpackY(Zr[c], Zr[4096 - c]);
            float2 Yc = unpackY(Zr[2048 - c], Zr[2048 + c]);
            float2 wm, wmir;
            c2rsplit(Ym, Yc, c1 * (float)(768 * c), wm, wmir);
            win[0][SW(c)] = wm;
            win[0][SW(2048 - c)] = wmir;
        }
        // row 384: c in [0,1023]
        const size_t base = (size_t)384 * N2;
        #pragma unroll
        for (int j = 0; j < 4; j++) {
            int c = t + (j << 8);              // [0,1023]
            float2 Ym = unpackY(Zr[base + c], Zr[base + 4095 - c]);
            float2 Yc = unpackY(Zr[base + 2047 - c], Zr[base + 2048 + c]);
            float2 wm, wmir;
            c2rsplit(Ym, Yc, c1 * (float)(384 + 768 * c), wm, wmir);
            win[1][SW(c)] = wm;
            win[1][SW(2047 - c)] = wmir;
        }
        if (t == 0) {
            float2 z0 = Zr[0], zh = Zr[2048];
            float Y0 = z0.x * z0.y;
            float Yh = zh.x * zh.y;
            win[0][SW(0)] = make_float2(0.5f * (Y0 + Yh), -0.5f * (Y0 - Yh));
        }
    } else {
        row0 = r; row1 = 768 - r;
        const size_t bR = (size_t)r * N2;
        const size_t bM = (size_t)(768 - r) * N2;
        #pragma unroll
        for (int j = 0; j < 8; j++) {
            int c = t + (j << 8);              // [0,2048)
            float2 Ym = unpackY(Zr[bR + c],        Zr[bM + 4095 - c]);
            float2 Yc = unpackY(Zr[bM + 2047 - c], Zr[bR + 2048 + c]);
            float2 wm, wmir;
            c2rsplit(Ym, Yc, c1 * (float)(r + 768 * c), wm, wmir);
            win[0][SW(c)] = wm;
            win[1][SW(2047 - c)] = wmir;
        }
    }
    __syncthreads();

    // Phase 2: two 128-thread groups, 2048-pt FFT each (16,16,8)
    int g = t >> 7;                // group 0/1
    int tl = t & 127;
    int n1 = g ? row1 : row0;
    float2* wi = win[g];
    float2* ba = bA[g];
    float2* orow = H + (size_t)n1 * N2V;
    float2 x[16], X[16];

    // stage 1: radix-16, s=1, p=tl
    #pragma unroll
    for (int u = 0; u < 16; u++) x[u] = wi[SW(tl + (u << 7))];
    dft16(x, X);
    {
        float2 w1 = twid((6.2831853071795865f / 2048.0f) * (float)tl);
        float2 cur = make_float2(1.0f, 0.0f);
        #pragma unroll
        for (int rr = 0; rr < 16; rr++) { ba[SW(16 * tl + rr)] = cmul(X[rr], cur); cur = cmul(cur, w1); }
    }
    __syncthreads();

    // stage 2: radix-16, s=16; writes back into win (dead after stage 1)
    #pragma unroll
    for (int u = 0; u < 16; u++) x[u] = ba[SW(tl + (u << 7))];
    dft16(x, X);
    {
        int q = tl & 15, p = tl >> 4;
        float2 w1 = twid((6.2831853071795865f / 128.0f) * (float)p);
        float2 cur = make_float2(1.0f, 0.0f);
        int base = q + (p << 8);
        #pragma unroll
        for (int rr = 0; rr < 16; rr++) { wi[SW(base + 16 * rr)] = cmul(X[rr], cur); cur = cmul(cur, w1); }
    }
    __syncthreads();

    // stage 3: radix-8 (p=0) + interdim twiddle e^{-2pi i n1 j2 / NH} + store
    {
        const float c0 = 6.2831853071795865f / (float)NH;
        float2 y[8], Y8[8];
        #pragma unroll
        for (int qq0 = 0; qq0 < 2; qq0++) {
            int q = tl + (qq0 << 7);
            #pragma unroll
            for (int u = 0; u < 8; u++) y[u] = wi[SW(q + (u << 8))];
            dft8(y, Y8);
            float2 cur = twid(c0 * (float)(n1 * q));     // n1*q < 2^22: exact
            float2 V   = twid(c0 * (float)(n1 << 8));
            #pragma unroll
            for (int rr = 0; rr < 8; rr++) { orow[q + (rr << 8)] = cmul(Y8[rr], cur); cur = cmul(cur, V); }
        }
    }
}

// ---------------- inverse cols: 768-pt over TILE=8 cols, stride N2V;
// emits y pairs (Re,-Im) windowed as float2 + fused max-abs
__global__ void fft_cols768v(const float2* __restrict__ in, float2* __restrict__ outv,
                             int lo, int hi) {
    extern __shared__ float2 sm[];
    float2* bA = sm;
    float2* bB = sm + SMPAD_C;
    int k20 = blockIdx.x * TILE;
    int t = threadIdx.x;
    int b = t & (TILE - 1), tt = t >> LOG2TILE;
    float2 x[16], X[16];

    #pragma unroll
    for (int u = 0; u < 16; u++)
        x[u] = in[(size_t)(tt + 48 * u) * N2V + k20 + b];
    dft16(x, X);
    {
        float2 w1 = twid((6.2831853071795865f / 768.0f) * (float)tt);
        float2 cur = make_float2(1.0f, 0.0f);
        #pragma unroll
        for (int r = 0; r < 16; r++) {
            bA[SW(((16 * tt + r) << LOG2TILE) + b)] = cmul(X[r], cur); cur = cmul(cur, w1);
        }
    }
    __syncthreads();

    #pragma unroll
    for (int u = 0; u < 16; u++) x[u] = bA[SW(((tt + 48 * u) << LOG2TILE) + b)];
    dft16(x, X);
    {
        int q = tt & 15, p = tt >> 4;
        float2 w1 = twid((6.2831853071795865f / 48.0f) * (float)p);
        float2 cur = make_float2(1.0f, 0.0f);
        int base = q + (p << 8);
        #pragma unroll
        for (int r = 0; r < 16; r++) {
            bB[SW(((base + 16 * r) << LOG2TILE) + b)] = cmul(X[r], cur); cur = cmul(cur, w1);
        }
    }
    __syncthreads();

    const float SQ32 = 0.86602540378443864676f;
    float lmax = 0.0f;
    unsigned wlen = (unsigned)(hi - lo);
    for (int q = tt; q < 256; q += 48) {
        float2 a  = bB[SW(((q      ) << LOG2TILE) + b)];
        float2 bb = bB[SW(((q + 256) << LOG2TILE) + b)];
        float2 c  = bB[SW(((q + 512) << LOG2TILE) + b)];
        float2 ts = make_float2(bb.x + c.x, bb.y + c.y);
        float2 u  = make_float2(bb.x - c.x, bb.y - c.y);
        float2 e0 = make_float2(a.x + ts.x, a.y + ts.y);
        float rx = a.x - 0.5f * ts.x, ry = a.y - 0.5f * ts.y;
        float2 e1 = make_float2(rx + SQ32 * u.y, ry - SQ32 * u.x);
        float2 e2 = make_float2(rx - SQ32 * u.y, ry + SQ32 * u.x);
        int kc = k20 + b;
        #pragma unroll
        for (int r = 0; r < 3; r++) {
            float2 e = (r == 0) ? e0 : (r == 1) ? e1 : e2;
            int m = kc + ((q + 256 * r) << 11);
            int j0 = 2 * m;
            float2 v = make_float2(e.x, -e.y);
            if (j0 + 1 >= lo && j0 < hi) outv[m] = v;
            if ((unsigned)(j0     - lo) < wlen) lmax = fmaxf(lmax, fabsf(v.x));
            if ((unsigned)(j0 + 1 - lo) < wlen) lmax = fmaxf(lmax, fabsf(v.y));
        }
    }
    #pragma unroll
    for (int off = 16; off > 0; off >>= 1)
        lmax = fmaxf(lmax, __shfl_xor_sync(0xffffffffu, lmax, off));
    __shared__ float wmax[12];
    int lane = t & 31, w = t >> 5;
    if (lane == 0) wmax[w] = lmax;
    __syncthreads();
    if (t == 0) {
        float mx = wmax[0];
        #pragma unroll
        for (int j = 1; j < 12; j++) mx = fmaxf(mx, wmax[j]);
        atomicMax(&g_max_bits, __float_as_uint(mx));   // values >= 0
    }
}

// ---------------- final: out[i] = y[M-1+i] / max
__global__ void final_kernel(const float* __restrict__ yf,
                             float* __restrict__ out, int N, int M) {
    int i = blockIdx.x * blockDim.x + threadIdx.x;
    if (i < N) {
        float mx = __uint_as_float(g_max_bits);
        out[i] = yf[(M - 1) + i] / mx;
    }
}

extern "C" void kernel_launch(void* const* d_in, const int* in_sizes, int n_in,
                              void* d_out, int out_size) {
    const float* audio = (const float*)d_in[0];
    const float* ir    = (const float*)d_in[1];
    const int N = in_sizes[0];
    const int M = in_sizes[1];
    float* out = (float*)d_out;

    float2 *A = nullptr, *B = nullptr;
    cudaGetSymbolAddress((void**)&A, g_bufA);
    cudaGetSymbolAddress((void**)&B, g_bufB);

    const int SMEM_R  = 2 * SMPAD_R  * (int)sizeof(float2);   // 67584
    const int SMEM_C  = 2 * SMPAD_C  * (int)sizeof(float2);   // 101376
    const int SMEM_SI = 4 * SMPAD_R2 * (int)sizeof(float2);   // 67584
    cudaFuncSetAttribute(fwd_cols768,  cudaFuncAttributeMaxDynamicSharedMemorySize, SMEM_C);
    cudaFuncSetAttribute(fwd_rows4096, cudaFuncAttributeMaxDynamicSharedMemorySize, SMEM_R);
    cudaFuncSetAttribute(spec_invrows, cudaFuncAttributeMaxDynamicSharedMemorySize, SMEM_SI);
    cudaFuncSetAttribute(fft_cols768v, cudaFuncAttributeMaxDynamicSharedMemorySize, SMEM_C);

    // forward: cols (direct input, pack fused) -> A (G), rows A -> B (Zrow)
    fwd_cols768<<<N2 / TILE, 384, SMEM_C>>>(audio, N, ir, M, A);
    fwd_rows4096<<<768, 256, SMEM_R>>>(A, B);

    // fused specmul + C2R + inverse row FFTs: B (Zrow) -> A (H)
    spec_invrows<<<384, 256, SMEM_SI>>>(B, A);

    // inverse cols: A -> B (y pairs + fused max)
    fft_cols768v<<<N2V / TILE, 384, SMEM_C>>>(A, B, M - 1, M - 1 + N);

    final_kernel<<<(N + 255) / 256, 256>>>((const float*)B, out, N, M);
}

// round 9
// speedup vs baseline: 4.4892x; 1.0995x over previous
#include <cuda_runtime.h>

// Reverb via four-step FFT convolution, cols-first, fused specmul+inverse-rows,
// single-buffer in-place smem FFT stages (read-regs -> sync -> write) to halve
// smem and raise occupancy.
// NFFT = 3*2^20 = 768*4096 >= N + 2(M-1); NH = NFFT/2 = 768*2048.

#define NFFT   3145728
#define NH     1572864
#define N2     4096
#define N2V    2048
#define TILE   8
#define LOG2TILE 3
#define SMPAD_R  4224         // SW(4095)=4222
#define SMPAD_R2 2112         // SW(2047)=2110
#define SMPAD_C  6336         // SW(6143)=6334

__device__ float2 g_bufA[1 << 22];
__device__ float2 g_bufB[1 << 22];
__device__ unsigned int g_max_bits;

__device__ __forceinline__ float2 cmul(float2 a, float2 b) {
    return make_float2(fmaf(a.x, b.x, -(a.y * b.y)),
                       fmaf(a.x, b.y,  (a.y * b.x)));
}
__device__ __forceinline__ float2 twid(float ang) {   // e^{-i ang}
    float sn, cs; __sincosf(ang, &sn, &cs);
    return make_float2(cs, -sn);
}
__device__ __forceinline__ int SW(int x) { return x + (x >> 5); }

__device__ __forceinline__ void r4core(float2 a, float2 b, float2 c, float2 d,
                                       float2& e0, float2& e1, float2& e2, float2& e3) {
    float2 apc = make_float2(a.x + c.x, a.y + c.y);
    float2 amc = make_float2(a.x - c.x, a.y - c.y);
    float2 bpd = make_float2(b.x + d.x, b.y + d.y);
    float2 bmd = make_float2(b.x - d.x, b.y - d.y);
    e0 = make_float2(apc.x + bpd.x, apc.y + bpd.y);
    e1 = make_float2(amc.x + bmd.y, amc.y - bmd.x);
    e2 = make_float2(apc.x - bpd.x, apc.y - bpd.y);
    e3 = make_float2(amc.x - bmd.y, amc.y + bmd.x);
}

__device__ __forceinline__ void dft16(const float2* x, float2* X) {
    const float C1 = 0.92387953251128675613f;
    const float S1 = 0.38268343236508977173f;
    const float R2 = 0.70710678118654752440f;
    float2 t0[4], t1[4], t2[4], t3[4];
    r4core(x[0], x[4], x[8],  x[12], t0[0], t0[1], t0[2], t0[3]);
    r4core(x[1], x[5], x[9],  x[13], t1[0], t1[1], t1[2], t1[3]);
    r4core(x[2], x[6], x[10], x[14], t2[0], t2[1], t2[2], t2[3]);
    r4core(x[3], x[7], x[11], x[15], t3[0], t3[1], t3[2], t3[3]);
    t1[1] = cmul(t1[1], make_float2( C1, -S1));
    t1[2] = cmul(t1[2], make_float2( R2, -R2));
    t1[3] = cmul(t1[3], make_float2( S1, -C1));
    t2[1] = cmul(t2[1], make_float2( R2, -R2));
    t2[2] = make_float2(t2[2].y, -t2[2].x);
    t2[3] = cmul(t2[3], make_float2(-R2, -R2));
    t3[1] = cmul(t3[1], make_float2( S1, -C1));
    t3[2] = cmul(t3[2], make_float2(-R2, -R2));
    t3[3] = cmul(t3[3], make_float2(-C1,  S1));
    r4core(t0[0], t1[0], t2[0], t3[0], X[0], X[4], X[8],  X[12]);
    r4core(t0[1], t1[1], t2[1], t3[1], X[1], X[5], X[9],  X[13]);
    r4core(t0[2], t1[2], t2[2], t3[2], X[2], X[6], X[10], X[14]);
    r4core(t0[3], t1[3], t2[3], t3[3], X[3], X[7], X[11], X[15]);
}

__device__ __forceinline__ void dft8(const float2* x, float2* X) {
    const float R2 = 0.70710678118654752440f;
    float2 E0, E1, E2, E3, O0, O1, O2, O3;
    r4core(x[0], x[2], x[4], x[6], E0, E1, E2, E3);
    r4core(x[1], x[3], x[5], x[7], O0, O1, O2, O3);
    float2 T1 = cmul(O1, make_float2( R2, -R2));
    float2 T2 = make_float2(O2.y, -O2.x);
    float2 T3 = cmul(O3, make_float2(-R2, -R2));
    X[0] = make_float2(E0.x + O0.x, E0.y + O0.y);
    X[4] = make_float2(E0.x - O0.x, E0.y - O0.y);
    X[1] = make_float2(E1.x + T1.x, E1.y + T1.y);
    X[5] = make_float2(E1.x - T1.x, E1.y - T1.y);
    X[2] = make_float2(E2.x + T2.x, E2.y + T2.y);
    X[6] = make_float2(E2.x - T2.x, E2.y - T2.y);
    X[3] = make_float2(E3.x + T3.x, E3.y + T3.y);
    X[7] = make_float2(E3.x - T3.x, E3.y - T3.y);
}

__device__ __forceinline__ float2 unpackY(float2 zk, float2 zn) {
    float2 A  = make_float2(0.5f * (zk.x + zn.x), 0.5f * (zk.y - zn.y));
    float2 Dv = make_float2(zk.x - zn.x, zk.y + zn.y);
    float2 H  = make_float2(0.5f * Dv.y, -0.5f * Dv.x);
    return cmul(A, H);
}

__device__ __forceinline__ void c2rsplit(float2 Ym, float2 Yc, float th,
                                         float2& wm, float2& wmir) {
    float2 E = make_float2(0.5f * (Ym.x + Yc.x), 0.5f * (Ym.y - Yc.y));
    float2 G = make_float2(0.5f * (Ym.x - Yc.x), 0.5f * (Ym.y + Yc.y));
    float sn, cs; __sincosf(th, &sn, &cs);
    float2 O = cmul(make_float2(cs, sn), G);
    wm   = make_float2(E.x - O.y, -E.y - O.x);
    wmir = make_float2(E.x + O.y,  E.y - O.x);
}

// ---------------- fwd_cols768: single smem buffer (SMPAD_C)
__global__ void fwd_cols768(const float* __restrict__ audio, int N,
                            const float* __restrict__ ir, int M,
                            float2* __restrict__ G) {
    extern __shared__ float2 bA[];
    int k20 = blockIdx.x * TILE;
    int t = threadIdx.x;
    int b = t & (TILE - 1), tt = t >> LOG2TILE;    // tt in [0,48)
    if (blockIdx.x == 0 && t == 0) g_max_bits = 0u;
    float2 x[16], X[16];

    // stage 1: gmem -> bA
    #pragma unroll
    for (int u = 0; u < 16; u++) {
        int n = (tt + 48 * u) * 4096 + k20 + b;
        float re = (n < N) ? audio[n] : 0.0f;
        float im = (n < M) ? ir[M - 1 - n] : 0.0f;
        x[u] = make_float2(re, im);
    }
    dft16(x, X);
    {
        float2 w1 = twid((6.2831853071795865f / 768.0f) * (float)tt);
        float2 cur = make_float2(1.0f, 0.0f);
        #pragma unroll
        for (int r = 0; r < 16; r++) {
            bA[SW(((16 * tt + r) << LOG2TILE) + b)] = cmul(X[r], cur); cur = cmul(cur, w1);
        }
    }
    __syncthreads();

    // stage 2: in-place (read all -> sync -> write all)
    #pragma unroll
    for (int u = 0; u < 16; u++) x[u] = bA[SW(((tt + 48 * u) << LOG2TILE) + b)];
    __syncthreads();
    dft16(x, X);
    {
        int q = tt & 15, p = tt >> 4;
        float2 w1 = twid((6.2831853071795865f / 48.0f) * (float)p);
        float2 cur = make_float2(1.0f, 0.0f);
        int base = q + (p << 8);
        #pragma unroll
        for (int r = 0; r < 16; r++) {
            bA[SW(((base + 16 * r) << LOG2TILE) + b)] = cmul(X[r], cur); cur = cmul(cur, w1);
        }
    }
    __syncthreads();

    // stage 3: radix-3 (p=0) + interdim twiddle + store
    const float SQ32 = 0.86602540378443864676f;
    const float c0 = 6.2831853071795865f / (float)NFFT;
    int kc = k20 + b;
    for (int q = tt; q < 256; q += 48) {
        float2 a  = bA[SW(((q      ) << LOG2TILE) + b)];
        float2 bb = bA[SW(((q + 256) << LOG2TILE) + b)];
        float2 c  = bA[SW(((q + 512) << LOG2TILE) + b)];
        float2 ts = make_float2(bb.x + c.x, bb.y + c.y);
        float2 u  = make_float2(bb.x - c.x, bb.y - c.y);
        float2 e0 = make_float2(a.x + ts.x, a.y + ts.y);
        float rx = a.x - 0.5f * ts.x, ry = a.y - 0.5f * ts.y;
        float2 e1 = make_float2(rx + SQ32 * u.y, ry - SQ32 * u.x);
        float2 e2 = make_float2(rx - SQ32 * u.y, ry + SQ32 * u.x);
        G[(size_t)(q      ) * N2 + kc] = cmul(e0, twid(c0 * (float)(kc * (q      ))));
        G[(size_t)(q + 256) * N2 + kc] = cmul(e1, twid(c0 * (float)(kc * (q + 256))));
        G[(size_t)(q + 512) * N2 + kc] = cmul(e2, twid(c0 * (float)(kc * (q + 512))));
    }
}

// ---------------- fwd_rows4096: single smem buffer (SMPAD_R)
__global__ void fwd_rows4096(const float2* __restrict__ in, float2* __restrict__ out) {
    extern __shared__ float2 bA[];
    int t = threadIdx.x;
    const float2* row = in + (size_t)blockIdx.x * N2;
    float2* orow = out + (size_t)blockIdx.x * N2;
    float2 x[16], X[16];

    #pragma unroll
    for (int u = 0; u < 16; u++) x[u] = row[t + (u << 8)];
    dft16(x, X);
    {
        float2 w1 = twid((6.2831853071795865f / 4096.0f) * (float)t);
        float2 cur = make_float2(1.0f, 0.0f);
        #pragma unroll
        for (int r = 0; r < 16; r++) { bA[SW(16 * t + r)] = cmul(X[r], cur); cur = cmul(cur, w1); }
    }
    __syncthreads();

    #pragma unroll
    for (int u = 0; u < 16; u++) x[u] = bA[SW(t + (u << 8))];
    __syncthreads();
    dft16(x, X);
    {
        int q = t & 15, p = t >> 4;
        float2 w1 = twid((6.2831853071795865f / 256.0f) * (float)p);
        float2 cur = make_float2(1.0f, 0.0f);
        int base = q + (p << 8);
        #pragma unroll
        for (int r = 0; r < 16; r++) { bA[SW(base + 16 * r)] = cmul(X[r], cur); cur = cmul(cur, w1); }
    }
    __syncthreads();

    #pragma unroll
    for (int u = 0; u < 16; u++) x[u] = bA[SW(t + (u << 8))];
    dft16(x, X);
    #pragma unroll
    for (int r = 0; r < 16; r++) orow[t + (r << 8)] = X[r];
}

// ---------------- spec_invrows: fused specmul + C2R + two 2048-pt FFTs.
// Single pair of row buffers (2 * SMPAD_R2); FFT stages run in-place.
__global__ void spec_invrows(const float2* __restrict__ Zr, float2* __restrict__ H) {
    extern __shared__ float2 sm[];
    float2* win[2] = { sm, sm + SMPAD_R2 };
    int t = threadIdx.x;
    int r = blockIdx.x;
    const float c1 = 6.2831853071795865f / (float)NFFT;

    int row0, row1;
    if (r == 0) {
        row0 = 0; row1 = 384;
        #pragma unroll
        for (int j = 0; j < 4; j++) {
            int c = 1 + t + (j << 8);          // [1,1024]
            float2 Ym = unpackY(Zr[c], Zr[4096 - c]);
            float2 Yc = unpackY(Zr[2048 - c], Zr[2048 + c]);
            float2 wm, wmir;
            c2rsplit(Ym, Yc, c1 * (float)(768 * c), wm, wmir);
            win[0][SW(c)] = wm;
            win[0][SW(2048 - c)] = wmir;
        }
        const size_t base = (size_t)384 * N2;
        #pragma unroll
        for (int j = 0; j < 4; j++) {
            int c = t + (j << 8);              // [0,1023]
            float2 Ym = unpackY(Zr[base + c], Zr[base + 4095 - c]);
            float2 Yc = unpackY(Zr[base + 2047 - c], Zr[base + 2048 + c]);
            float2 wm, wmir;
            c2rsplit(Ym, Yc, c1 * (float)(384 + 768 * c), wm, wmir);
            win[1][SW(c)] = wm;
            win[1][SW(2047 - c)] = wmir;
        }
        if (t == 0) {
            float2 z0 = Zr[0], zh = Zr[2048];
            float Y0 = z0.x * z0.y;
            float Yh = zh.x * zh.y;
            win[0][SW(0)] = make_float2(0.5f * (Y0 + Yh), -0.5f * (Y0 - Yh));
        }
    } else {
        row0 = r; row1 = 768 - r;
        const size_t bR = (size_t)r * N2;
        const size_t bM = (size_t)(768 - r) * N2;
        #pragma unroll
        for (int j = 0; j < 8; j++) {
            int c = t + (j << 8);              // [0,2048)
            float2 Ym = unpackY(Zr[bR + c],        Zr[bM + 4095 - c]);
            float2 Yc = unpackY(Zr[bM + 2047 - c], Zr[bR + 2048 + c]);
            float2 wm, wmir;
            c2rsplit(Ym, Yc, c1 * (float)(r + 768 * c), wm, wmir);
            win[0][SW(c)] = wm;
            win[1][SW(2047 - c)] = wmir;
        }
    }
    __syncthreads();

    // Phase 2: two 128-thread groups, 2048-pt FFT in-place in win[g]
    int g = t >> 7;
    int tl = t & 127;
    int n1 = g ? row1 : row0;
    float2* wi = win[g];
    float2* orow = H + (size_t)n1 * N2V;
    float2 x[16], X[16];

    // stage 1: radix-16, s=1, p=tl (in-place)
    #pragma unroll
    for (int u = 0; u < 16; u++) x[u] = wi[SW(tl + (u << 7))];
    __syncthreads();
    dft16(x, X);
    {
        float2 w1 = twid((6.2831853071795865f / 2048.0f) * (float)tl);
        float2 cur = make_float2(1.0f, 0.0f);
        #pragma unroll
        for (int rr = 0; rr < 16; rr++) { wi[SW(16 * tl + rr)] = cmul(X[rr], cur); cur = cmul(cur, w1); }
    }
    __syncthreads();

    // stage 2: radix-16, s=16 (in-place)
    #pragma unroll
    for (int u = 0; u < 16; u++) x[u] = wi[SW(tl + (u << 7))];
    __syncthreads();
    dft16(x, X);
    {
        int q = tl & 15, p = tl >> 4;
        float2 w1 = twid((6.2831853071795865f / 128.0f) * (float)p);
        float2 cur = make_float2(1.0f, 0.0f);
        int base = q + (p << 8);
        #pragma unroll
        for (int rr = 0; rr < 16; rr++) { wi[SW(base + 16 * rr)] = cmul(X[rr], cur); cur = cmul(cur, w1); }
    }
    __syncthreads();

    // stage 3: radix-8 (p=0) + interdim twiddle + store
    {
        const float c0 = 6.2831853071795865f / (float)NH;
        float2 y[8], Y8[8];
        #pragma unroll
        for (int qq0 = 0; qq0 < 2; qq0++) {
            int q = tl + (qq0 << 7);
            #pragma unroll
            for (int u = 0; u < 8; u++) y[u] = wi[SW(q + (u << 8))];
            dft8(y, Y8);
            float2 cur = twid(c0 * (float)(n1 * q));
            float2 V   = twid(c0 * (float)(n1 << 8));
            #pragma unroll
            for (int rr = 0; rr < 8; rr++) { orow[q + (rr << 8)] = cmul(Y8[rr], cur); cur = cmul(cur, V); }
        }
    }
}

// ---------------- inverse cols: single buffer, in-place stages
__global__ void fft_cols768v(const float2* __restrict__ in, float2* __restrict__ outv,
                             int lo, int hi) {
    extern __shared__ float2 bA[];
    int k20 = blockIdx.x * TILE;
    int t = threadIdx.x;
    int b = t & (TILE - 1), tt = t >> LOG2TILE;
    float2 x[16], X[16];

    #pragma unroll
    for (int u = 0; u < 16; u++)
        x[u] = in[(size_t)(tt + 48 * u) * N2V + k20 + b];
    dft16(x, X);
    {
        float2 w1 = twid((6.2831853071795865f / 768.0f) * (float)tt);
        float2 cur = make_float2(1.0f, 0.0f);
        #pragma unroll
        for (int r = 0; r < 16; r++) {
            bA[SW(((16 * tt + r) << LOG2TILE) + b)] = cmul(X[r], cur); cur = cmul(cur, w1);
        }
    }
    __syncthreads();

    #pragma unroll
    for (int u = 0; u < 16; u++) x[u] = bA[SW(((tt + 48 * u) << LOG2TILE) + b)];
    __syncthreads();
    dft16(x, X);
    {
        int q = tt & 15, p = tt >> 4;
        float2 w1 = twid((6.2831853071795865f / 48.0f) * (float)p);
        float2 cur = make_float2(1.0f, 0.0f);
        int base = q + (p << 8);
        #pragma unroll
        for (int r = 0; r < 16; r++) {
            bA[SW(((base + 16 * r) << LOG2TILE) + b)] = cmul(X[r], cur); cur = cmul(cur, w1);
        }
    }
    __syncthreads();

    const float SQ32 = 0.86602540378443864676f;
    float lmax = 0.0f;
    unsigned wlen = (unsigned)(hi - lo);
    for (int q = tt; q < 256; q += 48) {
        float2 a  = bA[SW(((q      ) << LOG2TILE) + b)];
        float2 bb = bA[SW(((q + 256) << LOG2TILE) + b)];
        float2 c  = bA[SW(((q + 512) << LOG2TILE) + b)];
        float2 ts = make_float2(bb.x + c.x, bb.y + c.y);
        float2 u  = make_float2(bb.x - c.x, bb.y - c.y);
        float2 e0 = make_float2(a.x + ts.x, a.y + ts.y);
        float rx = a.x - 0.5f * ts.x, ry = a.y - 0.5f * ts.y;
        float2 e1 = make_float2(rx + SQ32 * u.y, ry - SQ32 * u.x);
        float2 e2 = make_float2(rx - SQ32 * u.y, ry + SQ32 * u.x);
        int kc = k20 + b;
        #pragma unroll
        for (int r = 0; r < 3; r++) {
            float2 e = (r == 0) ? e0 : (r == 1) ? e1 : e2;
            int m = kc + ((q + 256 * r) << 11);
            int j0 = 2 * m;
            float2 v = make_float2(e.x, -e.y);
            if (j0 + 1 >= lo && j0 < hi) outv[m] = v;
            if ((unsigned)(j0     - lo) < wlen) lmax = fmaxf(lmax, fabsf(v.x));
            if ((unsigned)(j0 + 1 - lo) < wlen) lmax = fmaxf(lmax, fabsf(v.y));
        }
    }
    #pragma unroll
    for (int off = 16; off > 0; off >>= 1)
        lmax = fmaxf(lmax, __shfl_xor_sync(0xffffffffu, lmax, off));
    __shared__ float wmax[12];
    int lane = t & 31, w = t >> 5;
    if (lane == 0) wmax[w] = lmax;
    __syncthreads();
    if (t == 0) {
        float mx = wmax[0];
        #pragma unroll
        for (int j = 1; j < 12; j++) mx = fmaxf(mx, wmax[j]);
        atomicMax(&g_max_bits, __float_as_uint(mx));   // values >= 0
    }
}

// ---------------- final: out[i] = y[M-1+i] / max
__global__ void final_kernel(const float* __restrict__ yf,
                             float* __restrict__ out, int N, int M) {
    int i = blockIdx.x * blockDim.x + threadIdx.x;
    if (i < N) {
        float mx = __uint_as_float(g_max_bits);
        out[i] = yf[(M - 1) + i] / mx;
    }
}

extern "C" void kernel_launch(void* const* d_in, const int* in_sizes, int n_in,
                              void* d_out, int out_size) {
    const float* audio = (const float*)d_in[0];
    const float* ir    = (const float*)d_in[1];
    const int N = in_sizes[0];
    const int M = in_sizes[1];
    float* out = (float*)d_out;

    float2 *A = nullptr, *B = nullptr;
    cudaGetSymbolAddress((void**)&A, g_bufA);
    cudaGetSymbolAddress((void**)&B, g_bufB);

    const int SMEM_R  = SMPAD_R  * (int)sizeof(float2);      // 33792
    const int SMEM_C  = SMPAD_C  * (int)sizeof(float2);      // 50688
    const int SMEM_SI = 2 * SMPAD_R2 * (int)sizeof(float2);  // 33792
    cudaFuncSetAttribute(fwd_cols768,  cudaFuncAttributeMaxDynamicSharedMemorySize, SMEM_C);
    cudaFuncSetAttribute(fwd_rows4096, cudaFuncAttributeMaxDynamicSharedMemorySize, SMEM_R);
    cudaFuncSetAttribute(spec_invrows, cudaFuncAttributeMaxDynamicSharedMemorySize, SMEM_SI);
    cudaFuncSetAttribute(fft_cols768v, cudaFuncAttributeMaxDynamicSharedMemorySize, SMEM_C);

    // forward: cols (direct input, pack fused) -> A (G), rows A -> B (Zrow)
    fwd_cols768<<<N2 / TILE, 384, SMEM_C>>>(audio, N, ir, M, A);
    fwd_rows4096<<<768, 256, SMEM_R>>>(A, B);

    // fused specmul + C2R + inverse row FFTs: B (Zrow) -> A (H)
    spec_invrows<<<384, 256, SMEM_SI>>>(B, A);

    // inverse cols: A -> B (y pairs + fused max)
    fft_cols768v<<<N2V / TILE, 384, SMEM_C>>>(A, B, M - 1, M - 1 + N);

    final_kernel<<<(N + 255) / 256, 256>>>((const float*)B, out, N, M);
}

// round 10
// speedup vs baseline: 4.6681x; 1.0398x over previous
#include <cuda_runtime.h>

// Reverb via four-step FFT convolution, cols-first, fused specmul+inverse-rows,
// in-place smem FFT stages, shallow twiddle product-trees, incremental
// epilogue twiddles (minimal MUFU).
// NFFT = 3*2^20 = 768*4096 >= N + 2(M-1); NH = NFFT/2 = 768*2048.

#define NFFT   3145728
#define NH     1572864
#define N2     4096
#define N2V    2048
#define TILE   8
#define LOG2TILE 3
#define SMPAD_R  4224         // SW(4095)=4222
#define SMPAD_R2 2112         // SW(2047)=2110
#define SMPAD_C  6336         // SW(6143)=6334

__device__ float2 g_bufA[1 << 22];
__device__ float2 g_bufB[1 << 22];
__device__ unsigned int g_max_bits;

__device__ __forceinline__ float2 cmul(float2 a, float2 b) {
    return make_float2(fmaf(a.x, b.x, -(a.y * b.y)),
                       fmaf(a.x, b.y,  (a.y * b.x)));
}
__device__ __forceinline__ float2 twid(float ang) {   // e^{-i ang}
    float sn, cs; __sincosf(ang, &sn, &cs);
    return make_float2(cs, -sn);
}
__device__ __forceinline__ int SW(int x) { return x + (x >> 5); }

// tw[r] = w1^r for r in [0,16), depth <= 5 instead of a 15-deep chain
__device__ __forceinline__ void make_tw16(float2 w1, float2* tw) {
    tw[0] = make_float2(1.0f, 0.0f);
    tw[1] = w1;
    tw[2] = cmul(w1, w1);
    tw[3] = cmul(tw[2], w1);
    tw[4] = cmul(tw[2], tw[2]);
    tw[8] = cmul(tw[4], tw[4]);
    tw[12] = cmul(tw[8], tw[4]);
    tw[5]  = cmul(tw[4],  w1);
    tw[6]  = cmul(tw[4],  tw[2]);
    tw[7]  = cmul(tw[4],  tw[3]);
    tw[9]  = cmul(tw[8],  w1);
    tw[10] = cmul(tw[8],  tw[2]);
    tw[11] = cmul(tw[8],  tw[3]);
    tw[13] = cmul(tw[12], w1);
    tw[14] = cmul(tw[12], tw[2]);
    tw[15] = cmul(tw[12], tw[3]);
}

__device__ __forceinline__ void r4core(float2 a, float2 b, float2 c, float2 d,
                                       float2& e0, float2& e1, float2& e2, float2& e3) {
    float2 apc = make_float2(a.x + c.x, a.y + c.y);
    float2 amc = make_float2(a.x - c.x, a.y - c.y);
    float2 bpd = make_float2(b.x + d.x, b.y + d.y);
    float2 bmd = make_float2(b.x - d.x, b.y - d.y);
    e0 = make_float2(apc.x + bpd.x, apc.y + bpd.y);
    e1 = make_float2(amc.x + bmd.y, amc.y - bmd.x);
    e2 = make_float2(apc.x - bpd.x, apc.y - bpd.y);
    e3 = make_float2(amc.x - bmd.y, amc.y + bmd.x);
}

__device__ __forceinline__ void dft16(const float2* x, float2* X) {
    const float C1 = 0.92387953251128675613f;
    const float S1 = 0.38268343236508977173f;
    const float R2 = 0.70710678118654752440f;
    float2 t0[4], t1[4], t2[4], t3[4];
    r4core(x[0], x[4], x[8],  x[12], t0[0], t0[1], t0[2], t0[3]);
    r4core(x[1], x[5], x[9],  x[13], t1[0], t1[1], t1[2], t1[3]);
    r4core(x[2], x[6], x[10], x[14], t2[0], t2[1], t2[2], t2[3]);
    r4core(x[3], x[7], x[11], x[15], t3[0], t3[1], t3[2], t3[3]);
    t1[1] = cmul(t1[1], make_float2( C1, -S1));
    t1[2] = cmul(t1[2], make_float2( R2, -R2));
    t1[3] = cmul(t1[3], make_float2( S1, -C1));
    t2[1] = cmul(t2[1], make_float2( R2, -R2));
    t2[2] = make_float2(t2[2].y, -t2[2].x);
    t2[3] = cmul(t2[3], make_float2(-R2, -R2));
    t3[1] = cmul(t3[1], make_float2( S1, -C1));
    t3[2] = cmul(t3[2], make_float2(-R2, -R2));
    t3[3] = cmul(t3[3], make_float2(-C1,  S1));
    r4core(t0[0], t1[0], t2[0], t3[0], X[0], X[4], X[8],  X[12]);
    r4core(t0[1], t1[1], t2[1], t3[1], X[1], X[5], X[9],  X[13]);
    r4core(t0[2], t1[2], t2[2], t3[2], X[2], X[6], X[10], X[14]);
    r4core(t0[3], t1[3], t2[3], t3[3], X[3], X[7], X[11], X[15]);
}

__device__ __forceinline__ void dft8(const float2* x, float2* X) {
    const float R2 = 0.70710678118654752440f;
    float2 E0, E1, E2, E3, O0, O1, O2, O3;
    r4core(x[0], x[2], x[4], x[6], E0, E1, E2, E3);
    r4core(x[1], x[3], x[5], x[7], O0, O1, O2, O3);
    float2 T1 = cmul(O1, make_float2( R2, -R2));
    float2 T2 = make_float2(O2.y, -O2.x);
    float2 T3 = cmul(O3, make_float2(-R2, -R2));
    X[0] = make_float2(E0.x + O0.x, E0.y + O0.y);
    X[4] = make_float2(E0.x - O0.x, E0.y - O0.y);
    X[1] = make_float2(E1.x + T1.x, E1.y + T1.y);
    X[5] = make_float2(E1.x - T1.x, E1.y - T1.y);
    X[2] = make_float2(E2.x + T2.x, E2.y + T2.y);
    X[6] = make_float2(E2.x - T2.x, E2.y - T2.y);
    X[3] = make_float2(E3.x + T3.x, E3.y + T3.y);
    X[7] = make_float2(E3.x - T3.x, E3.y - T3.y);
}

__device__ __forceinline__ float2 unpackY(float2 zk, float2 zn) {
    float2 A  = make_float2(0.5f * (zk.x + zn.x), 0.5f * (zk.y - zn.y));
    float2 Dv = make_float2(zk.x - zn.x, zk.y + zn.y);
    float2 H  = make_float2(0.5f * Dv.y, -0.5f * Dv.x);
    return cmul(A, H);
}

__device__ __forceinline__ void c2rsplit(float2 Ym, float2 Yc, float th,
                                         float2& wm, float2& wmir) {
    float2 E = make_float2(0.5f * (Ym.x + Yc.x), 0.5f * (Ym.y - Yc.y));
    float2 G = make_float2(0.5f * (Ym.x - Yc.x), 0.5f * (Ym.y + Yc.y));
    float sn, cs; __sincosf(th, &sn, &cs);
    float2 O = cmul(make_float2(cs, sn), G);
    wm   = make_float2(E.x - O.y, -E.y - O.x);
    wmir = make_float2(E.x + O.y,  E.y - O.x);
}

// ---------------- fwd_cols768
__global__ void fwd_cols768(const float* __restrict__ audio, int N,
                            const float* __restrict__ ir, int M,
                            float2* __restrict__ G) {
    extern __shared__ float2 bA[];
    int k20 = blockIdx.x * TILE;
    int t = threadIdx.x;
    int b = t & (TILE - 1), tt = t >> LOG2TILE;    // tt in [0,48)
    if (blockIdx.x == 0 && t == 0) g_max_bits = 0u;
    float2 x[16], X[16], tw[16];

    // stage 1: gmem -> bA
    #pragma unroll
    for (int u = 0; u < 16; u++) {
        int n = (tt + 48 * u) * 4096 + k20 + b;
        float re = (n < N) ? audio[n] : 0.0f;
        float im = (n < M) ? ir[M - 1 - n] : 0.0f;
        x[u] = make_float2(re, im);
    }
    dft16(x, X);
    make_tw16(twid((6.2831853071795865f / 768.0f) * (float)tt), tw);
    bA[SW((16 * tt) << LOG2TILE) + 0 * 0 + ((0) )] = X[0];  // placeholder avoided below
    #pragma unroll
    for (int r = 0; r < 16; r++)
        bA[SW(((16 * tt + r) << LOG2TILE) + b)] = (r == 0) ? X[0] : cmul(X[r], tw[r]);
    __syncthreads();

    // stage 2: in-place
    #pragma unroll
    for (int u = 0; u < 16; u++) x[u] = bA[SW(((tt + 48 * u) << LOG2TILE) + b)];
    __syncthreads();
    dft16(x, X);
    {
        int q = tt & 15, p = tt >> 4;
        make_tw16(twid((6.2831853071795865f / 48.0f) * (float)p), tw);
        int base = q + (p << 8);
        #pragma unroll
        for (int r = 0; r < 16; r++)
            bA[SW(((base + 16 * r) << LOG2TILE) + b)] = (r == 0) ? X[0] : cmul(X[r], tw[r]);
    }
    __syncthreads();

    // stage 3: radix-3 (p=0) + incremental interdim twiddle + store
    const float SQ32 = 0.86602540378443864676f;
    const float c0 = 6.2831853071795865f / (float)NFFT;
    int kc = k20 + b;
    // all integer angle args < 2^24: float-exact
    float2 cur = twid(c0 * (float)(kc * tt));
    float2 S   = twid(c0 * (float)(kc * 48));
    float2 P1  = twid(c0 * (float)(kc * 256));
    float2 P2  = cmul(P1, P1);
    for (int q = tt; q < 256; q += 48) {
        float2 a  = bA[SW(((q      ) << LOG2TILE) + b)];
        float2 bb = bA[SW(((q + 256) << LOG2TILE) + b)];
        float2 c  = bA[SW(((q + 512) << LOG2TILE) + b)];
        float2 ts = make_float2(bb.x + c.x, bb.y + c.y);
        float2 u  = make_float2(bb.x - c.x, bb.y - c.y);
        float2 e0 = make_float2(a.x + ts.x, a.y + ts.y);
        float rx = a.x - 0.5f * ts.x, ry = a.y - 0.5f * ts.y;
        float2 e1 = make_float2(rx + SQ32 * u.y, ry - SQ32 * u.x);
        float2 e2 = make_float2(rx - SQ32 * u.y, ry + SQ32 * u.x);
        G[(size_t)(q      ) * N2 + kc] = cmul(e0, cur);
        G[(size_t)(q + 256) * N2 + kc] = cmul(e1, cmul(cur, P1));
        G[(size_t)(q + 512) * N2 + kc] = cmul(e2, cmul(cur, P2));
        cur = cmul(cur, S);
    }
}

// ---------------- fwd_rows4096
__global__ void fwd_rows4096(const float2* __restrict__ in, float2* __restrict__ out) {
    extern __shared__ float2 bA[];
    int t = threadIdx.x;
    const float2* row = in + (size_t)blockIdx.x * N2;
    float2* orow = out + (size_t)blockIdx.x * N2;
    float2 x[16], X[16], tw[16];

    #pragma unroll
    for (int u = 0; u < 16; u++) x[u] = row[t + (u << 8)];
    dft16(x, X);
    make_tw16(twid((6.2831853071795865f / 4096.0f) * (float)t), tw);
    #pragma unroll
    for (int r = 0; r < 16; r++)
        bA[SW(16 * t + r)] = (r == 0) ? X[0] : cmul(X[r], tw[r]);
    __syncthreads();

    #pragma unroll
    for (int u = 0; u < 16; u++) x[u] = bA[SW(t + (u << 8))];
    __syncthreads();
    dft16(x, X);
    {
        int q = t & 15, p = t >> 4;
        make_tw16(twid((6.2831853071795865f / 256.0f) * (float)p), tw);
        int base = q + (p << 8);
        #pragma unroll
        for (int r = 0; r < 16; r++)
            bA[SW(base + 16 * r)] = (r == 0) ? X[0] : cmul(X[r], tw[r]);
    }
    __syncthreads();

    #pragma unroll
    for (int u = 0; u < 16; u++) x[u] = bA[SW(t + (u << 8))];
    dft16(x, X);
    #pragma unroll
    for (int r = 0; r < 16; r++) orow[t + (r << 8)] = X[r];
}

// ---------------- spec_invrows: fused specmul + C2R + two 2048-pt FFTs
__global__ void spec_invrows(const float2* __restrict__ Zr, float2* __restrict__ H) {
    extern __shared__ float2 sm[];
    float2* win[2] = { sm, sm + SMPAD_R2 };
    int t = threadIdx.x;
    int r = blockIdx.x;
    const float c1 = 6.2831853071795865f / (float)NFFT;

    int row0, row1;
    if (r == 0) {
        row0 = 0; row1 = 384;
        #pragma unroll
        for (int j = 0; j < 4; j++) {
            int c = 1 + t + (j << 8);          // [1,1024]
            float2 Ym = unpackY(Zr[c], Zr[4096 - c]);
            float2 Yc = unpackY(Zr[2048 - c], Zr[2048 + c]);
            float2 wm, wmir;
            c2rsplit(Ym, Yc, c1 * (float)(768 * c), wm, wmir);
            win[0][SW(c)] = wm;
            win[0][SW(2048 - c)] = wmir;
        }
        const size_t base = (size_t)384 * N2;
        #pragma unroll
        for (int j = 0; j < 4; j++) {
            int c = t + (j << 8);              // [0,1023]
            float2 Ym = unpackY(Zr[base + c], Zr[base + 4095 - c]);
            float2 Yc = unpackY(Zr[base + 2047 - c], Zr[base + 2048 + c]);
            float2 wm, wmir;
            c2rsplit(Ym, Yc, c1 * (float)(384 + 768 * c), wm, wmir);
            win[1][SW(c)] = wm;
            win[1][SW(2047 - c)] = wmir;
        }
        if (t == 0) {
            float2 z0 = Zr[0], zh = Zr[2048];
            float Y0 = z0.x * z0.y;
            float Yh = zh.x * zh.y;
            win[0][SW(0)] = make_float2(0.5f * (Y0 + Yh), -0.5f * (Y0 - Yh));
        }
    } else {
        row0 = r; row1 = 768 - r;
        const size_t bR = (size_t)r * N2;
        const size_t bM = (size_t)(768 - r) * N2;
        #pragma unroll
        for (int j = 0; j < 8; j++) {
            int c = t + (j << 8);              // [0,2048)
            float2 Ym = unpackY(Zr[bR + c],        Zr[bM + 4095 - c]);
            float2 Yc = unpackY(Zr[bM + 2047 - c], Zr[bR + 2048 + c]);
            float2 wm, wmir;
            c2rsplit(Ym, Yc, c1 * (float)(r + 768 * c), wm, wmir);
            win[0][SW(c)] = wm;
            win[1][SW(2047 - c)] = wmir;
        }
    }
    __syncthreads();

    // Phase 2: two 128-thread groups, 2048-pt FFT in-place
    int g = t >> 7;
    int tl = t & 127;
    int n1 = g ? row1 : row0;
    float2* wi = win[g];
    float2* orow = H + (size_t)n1 * N2V;
    float2 x[16], X[16], tw[16];

    #pragma unroll
    for (int u = 0; u < 16; u++) x[u] = wi[SW(tl + (u << 7))];
    __syncthreads();
    dft16(x, X);
    make_tw16(twid((6.2831853071795865f / 2048.0f) * (float)tl), tw);
    #pragma unroll
    for (int rr = 0; rr < 16; rr++)
        wi[SW(16 * tl + rr)] = (rr == 0) ? X[0] : cmul(X[rr], tw[rr]);
    __syncthreads();

    #pragma unroll
    for (int u = 0; u < 16; u++) x[u] = wi[SW(tl + (u << 7))];
    __syncthreads();
    dft16(x, X);
    {
        int q = tl & 15, p = tl >> 4;
        make_tw16(twid((6.2831853071795865f / 128.0f) * (float)p), tw);
        int base = q + (p << 8);
        #pragma unroll
        for (int rr = 0; rr < 16; rr++)
            wi[SW(base + 16 * rr)] = (rr == 0) ? X[0] : cmul(X[rr], tw[rr]);
    }
    __syncthreads();

    // stage 3: radix-8 (p=0) + interdim twiddle + store
    {
        const float c0 = 6.2831853071795865f / (float)NH;
        float2 y[8], Y8[8];
        #pragma unroll
        for (int qq0 = 0; qq0 < 2; qq0++) {
            int q = tl + (qq0 << 7);
            #pragma unroll
            for (int u = 0; u < 8; u++) y[u] = wi[SW(q + (u << 8))];
            dft8(y, Y8);
            float2 V  = twid(c0 * (float)(n1 << 8));
            float2 V2 = cmul(V, V);
            float2 V4 = cmul(V2, V2);
            float2 base0 = twid(c0 * (float)(n1 * q));
            float2 vv[8];
            vv[0] = base0;
            vv[1] = cmul(base0, V);
            vv[2] = cmul(base0, V2);
            vv[3] = cmul(vv[2], V);
            vv[4] = cmul(base0, V4);
            vv[5] = cmul(vv[4], V);
            vv[6] = cmul(vv[4], V2);
            vv[7] = cmul(vv[6], V);
            #pragma unroll
            for (int rr = 0; rr < 8; rr++) orow[q + (rr << 8)] = cmul(Y8[rr], vv[rr]);
        }
    }
}

// ---------------- inverse cols
__global__ void fft_cols768v(const float2* __restrict__ in, float2* __restrict__ outv,
                             int lo, int hi) {
    extern __shared__ float2 bA[];
    int k20 = blockIdx.x * TILE;
    int t = threadIdx.x;
    int b = t & (TILE - 1), tt = t >> LOG2TILE;
    float2 x[16], X[16], tw[16];

    #pragma unroll
    for (int u = 0; u < 16; u++)
        x[u] = in[(size_t)(tt + 48 * u) * N2V + k20 + b];
    dft16(x, X);
    make_tw16(twid((6.2831853071795865f / 768.0f) * (float)tt), tw);
    #pragma unroll
    for (int r = 0; r < 16; r++)
        bA[SW(((16 * tt + r) << LOG2TILE) + b)] = (r == 0) ? X[0] : cmul(X[r], tw[r]);
    __syncthreads();

    #pragma unroll
    for (int u = 0; u < 16; u++) x[u] = bA[SW(((tt + 48 * u) << LOG2TILE) + b)];
    __syncthreads();
    dft16(x, X);
    {
        int q = tt & 15, p = tt >> 4;
        make_tw16(twid((6.2831853071795865f / 48.0f) * (float)p), tw);
        int base = q + (p << 8);
        #pragma unroll
        for (int r = 0; r < 16; r++)
            bA[SW(((base + 16 * r) << LOG2TILE) + b)] = (r == 0) ? X[0] : cmul(X[r], tw[r]);
    }
    __syncthreads();

    const float SQ32 = 0.86602540378443864676f;
    float lmax = 0.0f;
    unsigned wlen = (unsigned)(hi - lo);
    for (int q = tt; q < 256; q += 48) {
        float2 a  = bA[SW(((q      ) << LOG2TILE) + b)];
        float2 bb = bA[SW(((q + 256) << LOG2TILE) + b)];
        float2 c  = bA[SW(((q + 512) << LOG2TILE) + b)];
        float2 ts = make_float2(bb.x + c.x, bb.y + c.y);
        float2 u  = make_float2(bb.x - c.x, bb.y - c.y);
        float2 e0 = make_float2(a.x + ts.x, a.y + ts.y);
        float rx = a.x - 0.5f * ts.x, ry = a.y - 0.5f * ts.y;
        float2 e1 = make_float2(rx + SQ32 * u.y, ry - SQ32 * u.x);
        float2 e2 = make_float2(rx - SQ32 * u.y, ry + SQ32 * u.x);
        int kc = k20 + b;
        #pragma unroll
        for (int r = 0; r < 3; r++) {
            float2 e = (r == 0) ? e0 : (r == 1) ? e1 : e2;
            int m = kc + ((q + 256 * r) << 11);
            int j0 = 2 * m;
            float2 v = make_float2(e.x, -e.y);
            if (j0 + 1 >= lo && j0 < hi) outv[m] = v;
            if ((unsigned)(j0     - lo) < wlen) lmax = fmaxf(lmax, fabsf(v.x));
            if ((unsigned)(j0 + 1 - lo) < wlen) lmax = fmaxf(lmax, fabsf(v.y));
        }
    }
    #pragma unroll
    for (int off = 16; off > 0; off >>= 1)
        lmax = fmaxf(lmax, __shfl_xor_sync(0xffffffffu, lmax, off));
    __shared__ float wmax[12];
    int lane = t & 31, w = t >> 5;
    if (lane == 0) wmax[w] = lmax;
    __syncthreads();
    if (t == 0) {
        float mx = wmax[0];
        #pragma unroll
        for (int j = 1; j < 12; j++) mx = fmaxf(mx, wmax[j]);
        atomicMax(&g_max_bits, __float_as_uint(mx));   // values >= 0
    }
}

// ---------------- final: out[i] = y[M-1+i] * (1/max), float4 stores
__global__ void final_kernel(const float* __restrict__ yf,
                             float* __restrict__ out, int N, int M) {
    int i4 = (blockIdx.x * blockDim.x + threadIdx.x) << 2;
    if (i4 >= N) return;
    float inv = 1.0f / __uint_as_float(g_max_bits);
    const float* src = yf + (M - 1) + i4;
    if (i4 + 3 < N) {
        float4 v;
        v.x = src[0] * inv;
        v.y = src[1] * inv;
        v.z = src[2] * inv;
        v.w = src[3] * inv;
        *reinterpret_cast<float4*>(out + i4) = v;
    } else {
        for (int j = 0; i4 + j < N; j++) out[i4 + j] = src[j] * inv;
    }
}

extern "C" void kernel_launch(void* const* d_in, const int* in_sizes, int n_in,
                              void* d_out, int out_size) {
    const float* audio = (const float*)d_in[0];
    const float* ir    = (const float*)d_in[1];
    const int N = in_sizes[0];
    const int M = in_sizes[1];
    float* out = (float*)d_out;

    float2 *A = nullptr, *B = nullptr;
    cudaGetSymbolAddress((void**)&A, g_bufA);
    cudaGetSymbolAddress((void**)&B, g_bufB);

    const int SMEM_R  = SMPAD_R  * (int)sizeof(float2);      // 33792
    const int SMEM_C  = SMPAD_C  * (int)sizeof(float2);      // 50688
    const int SMEM_SI = 2 * SMPAD_R2 * (int)sizeof(float2);  // 33792
    cudaFuncSetAttribute(fwd_cols768,  cudaFuncAttributeMaxDynamicSharedMemorySize, SMEM_C);
    cudaFuncSetAttribute(fwd_rows4096, cudaFuncAttributeMaxDynamicSharedMemorySize, SMEM_R);
    cudaFuncSetAttribute(spec_invrows, cudaFuncAttributeMaxDynamicSharedMemorySize, SMEM_SI);
    cudaFuncSetAttribute(fft_cols768v, cudaFuncAttributeMaxDynamicSharedMemorySize, SMEM_C);

    // forward: cols (direct input, pack fused) -> A (G), rows A -> B (Zrow)
    fwd_cols768<<<N2 / TILE, 384, SMEM_C>>>(audio, N, ir, M, A);
    fwd_rows4096<<<768, 256, SMEM_R>>>(A, B);

    // fused specmul + C2R + inverse row FFTs: B (Zrow) -> A (H)
    spec_invrows<<<384, 256, SMEM_SI>>>(B, A);

    // inverse cols: A -> B (y pairs + fused max)
    fft_cols768v<<<N2V / TILE, 384, SMEM_C>>>(A, B, M - 1, M - 1 + N);

    final_kernel<<<(N / 4 + 255) / 256, 256>>>((const float*)B, out, N, M);
}